// round 7
// baseline (speedup 1.0000x reference)
#include <cuda_runtime.h>

typedef unsigned long long ull;

#define Hs      49
#define HP      64
#define G4      196
#define NL      7
#define IN0     7
#define NOUT    7
#define BATCH   1024
#define TT      512

// ---------------- device scratch ------------------------------------------
__device__ float g_wrecc[NL][Hs][Hs][4];  // recurrent W compact: [l][k][u][gate]
__device__ float g_wxc[NL][Hs][Hs][4];    // input W compact: [l][k][u][gate]
__device__ float g_bias[NL][HP][4];       // b_ih+b_hh (u padded to 64)
__device__ float g_pre[TT][Hs][BATCH][4]; // input projections [t][u][b][gate]
__device__ float g_h[TT][BATCH][Hs];      // layer output [t][b][u]

// ---------------- f32x2 + fast-activation helpers --------------------------
static __device__ __forceinline__ ull pack2(float lo, float hi) {
    ull r; asm("mov.b64 %0, {%1,%2};" : "=l"(r) : "f"(lo), "f"(hi)); return r;
}
static __device__ __forceinline__ void unpack2(ull v, float &lo, float &hi) {
    asm("mov.b64 {%0,%1}, %2;" : "=f"(lo), "=f"(hi) : "l"(v));
}
static __device__ __forceinline__ ull ffma2(ull a, ull b, ull c) {
    ull d; asm("fma.rn.f32x2 %0, %1, %2, %3;" : "=l"(d) : "l"(a), "l"(b), "l"(c)); return d;
}
static __device__ __forceinline__ ull addf2(ull a, ull b) {
    ull d; asm("add.rn.f32x2 %0, %1, %2;" : "=l"(d) : "l"(a), "l"(b)); return d;
}
static __device__ __forceinline__ float ex2f(float x) {
    float r; asm("ex2.approx.f32 %0, %1;" : "=f"(r) : "f"(x)); return r;
}
static __device__ __forceinline__ float rcpf(float x) {
    float r; asm("rcp.approx.f32 %0, %1;" : "=f"(r) : "f"(x)); return r;
}
#define LOG2E 1.4426950408889634f
static __device__ __forceinline__ float sigf(float x) {
    return rcpf(1.f + ex2f(-LOG2E * x));
}
static __device__ __forceinline__ float tanhf2(float x) {
    return 1.f - 2.f * rcpf(1.f + ex2f(2.f * LOG2E * x));
}

// ---------------- weight / bias packing -----------------------------------
__global__ void pack_kernel(const float* __restrict__ W_ih0,
                            const float* __restrict__ W_ihr,
                            const float* __restrict__ W_hh,
                            const float* __restrict__ b_ih,
                            const float* __restrict__ b_hh) {
    int idx = blockIdx.x * blockDim.x + threadIdx.x;
    const int total = NL * Hs * HP * 4;   // k<49, u<64
    if (idx >= total) return;
    int l   = idx / (Hs * HP * 4);
    int rem = idx % (Hs * HP * 4);
    int k   = rem / (HP * 4);
    int ug  = rem % (HP * 4);
    int u = ug >> 2, j = ug & 3;
    int row = j * Hs + u;                 // torch gate order i,f,g,o

    if (u < Hs) {
        g_wrecc[l][k][u][j] = W_hh[(l * G4 + row) * Hs + k];
        float wx = 0.f;
        if (l == 0) {
            if (k < IN0) wx = W_ih0[row * IN0 + k];
        } else {
            wx = W_ihr[((l - 1) * G4 + row) * Hs + k];
        }
        g_wxc[l][k][u][j] = wx;
    }
    if (k == 0)
        g_bias[l][u][j] = (u < Hs) ? (b_ih[l * G4 + row] + b_hh[l * G4 + row]) : 0.f;
}

// ---------------- input-projection GEMM v3 ----------------------------------
// pre[t][u][b][j] = bias[u][j] + sum_k in[t][b][k] * Wx[k][u][j]
// 256 thr = 8 warps; thread = (u, 16 batch rows). Double-buffered input tile,
// ONE barrier per timestep. No index arrays (regs freed), 3 blocks/SM.
#define PG_TPB  256
#define PG_BT   64
#define PG_TS   8
#define ITP     68   // staged k-row stride in floats (272B, 16B aligned)

template<int KD, int KPAD, int KSH>
__global__ __launch_bounds__(PG_TPB, 3)
void pre_gemm3(const float* __restrict__ xin, int layer) {
    extern __shared__ float sm[];
    float* ws = sm;                      // [KD][49][4]
    float* bi = ws + KD * Hs * 4;        // [64][4]
    float* it = bi + HP * 4;             // [2][KD][ITP]

    const int tid = threadIdx.x;
    const float* wsrc = &g_wxc[layer][0][0][0];
    for (int i = tid; i < KD * Hs * 4; i += PG_TPB) ws[i] = wsrc[i];
    const float* bsrc = &g_bias[layer][0][0];
    for (int i = tid; i < HP * 4; i += PG_TPB) bi[i] = bsrc[i];

    const int warp = tid >> 5, lane = tid & 31;
    const int u  = (warp << 3) | (lane >> 2);
    const int bq = lane & 3;
    const int bbase = blockIdx.x * PG_BT;
    const int t0    = blockIdx.y * PG_TS;

    const int NI = (PG_BT * KPAD) / PG_TPB;   // staging iters (16 or 2)
    const long long tstr = (layer == 0) ? (long long)IN0 : (long long)BATCH * Hs;
    const float* src = (layer == 0) ? xin : &g_h[0][0][0];

    float xr[NI];
    // stage tile t0 into buffer 0
#pragma unroll
    for (int r = 0; r < NI; r++) {
        int i = tid + r * PG_TPB;
        int bb = i >> KSH, k = i & (KPAD - 1);
        if (k < KD) {
            long long go = (layer == 0)
                ? ((long long)(bbase + bb) * TT * IN0 + k)
                : ((long long)(bbase + bb) * Hs + k);
            xr[r] = src[go + (long long)t0 * tstr];
        }
    }
    __syncthreads();   // ws/bi staged
#pragma unroll
    for (int r = 0; r < NI; r++) {
        int i = tid + r * PG_TPB;
        int bb = i >> KSH, k = i & (KPAD - 1);
        if (k < KD) it[k * ITP + bb] = xr[r];
    }
    __syncthreads();

    ull bia[4];
    {
        float4 bv = *(float4*)(bi + u * 4);
        bia[0] = pack2(bv.x, bv.x); bia[1] = pack2(bv.y, bv.y);
        bia[2] = pack2(bv.z, bv.z); bia[3] = pack2(bv.w, bv.w);
    }

    for (int ti = 0; ti < PG_TS; ti++) {
        const int t = t0 + ti;
        const float* itc = it + (ti & 1) * KD * ITP;
        float* itn = it + ((ti + 1) & 1) * KD * ITP;

        // register-prefetch next tile
        if (ti + 1 < PG_TS) {
#pragma unroll
            for (int r = 0; r < NI; r++) {
                int i = tid + r * PG_TPB;
                int bb = i >> KSH, k = i & (KPAD - 1);
                if (k < KD) {
                    long long go = (layer == 0)
                        ? ((long long)(bbase + bb) * TT * IN0 + k)
                        : ((long long)(bbase + bb) * Hs + k);
                    xr[r] = src[go + (long long)(t + 1) * tstr];
                }
            }
        }

        ulonglong2 acc[4][4];
#pragma unroll
        for (int g = 0; g < 4; g++)
#pragma unroll
            for (int j = 0; j < 4; j++) { acc[g][j].x = bia[g]; acc[g][j].y = bia[g]; }

#pragma unroll 7
        for (int k = 0; k < KD; k++) {
            float4 w = *(float4*)(ws + (k * Hs + u) * 4);
            ull w0 = pack2(w.x, w.x), w1 = pack2(w.y, w.y);
            ull w2 = pack2(w.z, w.z), w3 = pack2(w.w, w.w);
#pragma unroll
            for (int j = 0; j < 4; j++) {
                ulonglong2 X = *(const ulonglong2*)(itc + k * ITP + bq * 16 + j * 4);
                acc[0][j].x = ffma2(w0, X.x, acc[0][j].x);
                acc[0][j].y = ffma2(w0, X.y, acc[0][j].y);
                acc[1][j].x = ffma2(w1, X.x, acc[1][j].x);
                acc[1][j].y = ffma2(w1, X.y, acc[1][j].y);
                acc[2][j].x = ffma2(w2, X.x, acc[2][j].x);
                acc[2][j].y = ffma2(w2, X.y, acc[2][j].y);
                acc[3][j].x = ffma2(w3, X.x, acc[3][j].x);
                acc[3][j].y = ffma2(w3, X.y, acc[3][j].y);
            }
        }

        if (u < Hs) {
#pragma unroll
            for (int j = 0; j < 4; j++) {
                float iv[4], fv[4], gv[4], ov[4];
                unpack2(acc[0][j].x, iv[0], iv[1]); unpack2(acc[0][j].y, iv[2], iv[3]);
                unpack2(acc[1][j].x, fv[0], fv[1]); unpack2(acc[1][j].y, fv[2], fv[3]);
                unpack2(acc[2][j].x, gv[0], gv[1]); unpack2(acc[2][j].y, gv[2], gv[3]);
                unpack2(acc[3][j].x, ov[0], ov[1]); unpack2(acc[3][j].y, ov[2], ov[3]);
#pragma unroll
                for (int e = 0; e < 4; e++) {
                    int b = bbase + bq * 16 + j * 4 + e;
                    *(float4*)&g_pre[t][u][b][0] = make_float4(iv[e], fv[e], gv[e], ov[e]);
                }
            }
        }

        // commit prefetched tile into the other buffer, single barrier
        if (ti + 1 < PG_TS) {
#pragma unroll
            for (int r = 0; r < NI; r++) {
                int i = tid + r * PG_TPB;
                int bb = i >> KSH, k = i & (KPAD - 1);
                if (k < KD) itn[k * ITP + bb] = xr[r];
            }
        }
        __syncthreads();
    }
}

// ---------------- recurrent kernel v3 ---------------------------------------
// 128 blocks x 672 threads (21 warps). Warps 0-6 (A): k [0,17); 7-13 (B): [17,33);
// 14-20 (C): [33,49). B,C write partials to smem; A combines + cell update.
#define R_TPB   672
#define R_SMEM  ((Hs*Hs*4 + 2*Hs*16 + 2*224*8) * 4)

__global__ __launch_bounds__(R_TPB, 1)
void lstm_rec3(int layer) {
    extern __shared__ float sm[];
    float* ws  = sm;                       // [49][49][4]
    float* vv  = ws + Hs * Hs * 4;         // [2][49][8][2] h duplicated pairs
    float* red = vv + 2 * Hs * 16;         // [2][224][8] partials (B, C)

    const int tid = threadIdx.x;
    const float* wsrc = &g_wrecc[layer][0][0][0];
    for (int i = tid; i < Hs * Hs * 4; i += R_TPB) ws[i] = wsrc[i];
    for (int i = tid; i < 2 * Hs * 16; i += R_TPB) vv[i] = 0.f;

    const int w    = tid >> 5, lane = tid & 31;
    const int grp  = w / 7;                // 0,1,2
    const int wu   = w % 7;
    const int u    = (wu << 3) | (lane >> 2);
    const int bp   = lane & 3;
    const int b0   = blockIdx.x * 8 + bp * 2;
    const bool act = (u < Hs);
    const int widx = wu * 32 + lane;       // 0..223

    __syncthreads();

    const ulonglong2* wp = (const ulonglong2*)ws;       // idx k*49 + u
    const long long pstride2 = (long long)Hs * BATCH;   // g_pre per-t stride, 16B units

    ull pf0 = 0, pf1 = 0, pf2 = 0, pf3 = 0;
    const ulonglong2* pp0 = (const ulonglong2*)&g_pre[0][act ? u : 0][b0][0];
    if (grp == 0 && act) {
        ulonglong2 A = pp0[0], B = pp0[1];
        pf0 = A.x; pf1 = A.y; pf2 = B.x; pf3 = B.y;
    }

    const int klo = (grp == 0) ? 0  : (grp == 1 ? 17 : 33);
    const int khi = (grp == 0) ? 17 : (grp == 1 ? 33 : 49);

    float c0 = 0.f, c1 = 0.f;

    for (int t = 0; t < TT; t++) {
        const int cur = t & 1, nxt = cur ^ 1;

        ull acc0, acc1, acc2, acc3;
        if (grp == 0) {
            acc0 = pf0; acc1 = pf1; acc2 = pf2; acc3 = pf3;
            if (act && t + 1 < TT) {      // prefetch pre(t+1)
                const ulonglong2* pp = pp0 + (long long)(t + 1) * pstride2;
                ulonglong2 A = pp[0], B = pp[1];
                pf0 = A.x; pf1 = A.y; pf2 = B.x; pf3 = B.y;
            }
        } else {
            acc0 = acc1 = acc2 = acc3 = 0;
        }

        if (act) {
            const ulonglong2* hp = (const ulonglong2*)(vv + cur * Hs * 16);
#pragma unroll 4
            for (int k = klo; k < khi; k++) {
                ulonglong2 W = wp[k * Hs + u];     // (wi,wf),(wg,wo)
                ulonglong2 H = hp[k * 4 + bp];     // (h0,h0),(h1,h1)
                acc0 = ffma2(W.x, H.x, acc0);
                acc1 = ffma2(W.y, H.x, acc1);
                acc2 = ffma2(W.x, H.y, acc2);
                acc3 = ffma2(W.y, H.y, acc3);
            }
            if (grp != 0) {
                ulonglong2* r = (ulonglong2*)(red + ((grp - 1) * 224 + widx) * 8);
                r[0] = make_ulonglong2(acc0, acc1);
                r[1] = make_ulonglong2(acc2, acc3);
            }
        }
        __syncthreads();   // partials visible

        if (grp == 0 && act) {
            const ulonglong2* r1 = (const ulonglong2*)(red + widx * 8);
            const ulonglong2* r2 = (const ulonglong2*)(red + (224 + widx) * 8);
            ulonglong2 Ra = r1[0], Rb = r1[1], Rc = r2[0], Rd = r2[1];
            acc0 = addf2(addf2(acc0, Ra.x), Rc.x);
            acc1 = addf2(addf2(acc1, Ra.y), Rc.y);
            acc2 = addf2(addf2(acc2, Rb.x), Rd.x);
            acc3 = addf2(addf2(acc3, Rb.y), Rd.y);

            float i0, f0, g0, o0, i1, f1, g1, o1;
            unpack2(acc0, i0, f0);
            unpack2(acc1, g0, o0);
            unpack2(acc2, i1, f1);
            unpack2(acc3, g1, o1);
            i0 = sigf(i0); f0 = sigf(f0); g0 = tanhf2(g0); o0 = sigf(o0);
            i1 = sigf(i1); f1 = sigf(f1); g1 = tanhf2(g1); o1 = sigf(o1);
            c0 = f0 * c0 + i0 * g0;
            c1 = f1 * c1 + i1 * g1;
            float h0v = o0 * tanhf2(c0);
            float h1v = o1 * tanhf2(c1);

            *((float4*)(vv + (nxt * Hs + u) * 16) + bp) = make_float4(h0v, h0v, h1v, h1v);
            g_h[t][b0][u]     = h0v;
            g_h[t][b0 + 1][u] = h1v;
        }
        __syncthreads();   // h(nxt) visible to all
    }
}

// ---------------- final FC --------------------------------------------------
#define FCB 128
__global__ void fc_kernel(const float* __restrict__ fc_w,
                          const float* __restrict__ fc_b,
                          float* __restrict__ outp) {
    __shared__ float sh[FCB * Hs];
    __shared__ float sw[NOUT * Hs + NOUT];
    int t   = blockIdx.x;
    int bc  = blockIdx.y;
    int tid = threadIdx.x;

    const float* hbuf = &g_h[0][0][0];
    for (int i = tid; i < FCB * Hs; i += FCB)
        sh[i] = hbuf[(long long)t * BATCH * Hs + (long long)bc * FCB * Hs + i];
    for (int i = tid; i < NOUT * Hs; i += FCB) sw[i] = fc_w[i];
    if (tid < NOUT) sw[NOUT * Hs + tid] = fc_b[tid];
    __syncthreads();

    int b = bc * FCB + tid;
    float o[NOUT];
#pragma unroll
    for (int j = 0; j < NOUT; j++) o[j] = sw[NOUT * Hs + j];
#pragma unroll
    for (int k = 0; k < Hs; k++) {
        float h = sh[tid * Hs + k];
#pragma unroll
        for (int j = 0; j < NOUT; j++) o[j] += h * sw[j * Hs + k];
    }
#pragma unroll
    for (int j = 0; j < NOUT; j++)
        outp[(long long)b * TT * NOUT + t * NOUT + j] = o[j];
}

// ---------------- launcher --------------------------------------------------
extern "C" void kernel_launch(void* const* d_in, const int* in_sizes, int n_in,
                              void* d_out, int out_size) {
    const float* x     = (const float*)d_in[0];
    const float* W_ih0 = (const float*)d_in[1];
    const float* W_ihr = (const float*)d_in[2];
    const float* W_hh  = (const float*)d_in[3];
    const float* b_ih  = (const float*)d_in[4];
    const float* b_hh  = (const float*)d_in[5];
    const float* fc_w  = (const float*)d_in[6];
    const float* fc_b  = (const float*)d_in[7];
    float* outp = (float*)d_out;

    const int pg_smem49 = (49 * Hs * 4 + HP * 4 + 2 * 49 * ITP) * 4;
    const int pg_smem7  = (7  * Hs * 4 + HP * 4 + 2 * 7  * ITP) * 4;
    cudaFuncSetAttribute((void*)pre_gemm3<49, 64, 6>,
                         cudaFuncAttributeMaxDynamicSharedMemorySize, pg_smem49);
    cudaFuncSetAttribute((void*)pre_gemm3<7, 8, 3>,
                         cudaFuncAttributeMaxDynamicSharedMemorySize, pg_smem7);
    cudaFuncSetAttribute((void*)lstm_rec3,
                         cudaFuncAttributeMaxDynamicSharedMemorySize, R_SMEM);

    const int total = NL * Hs * HP * 4;
    pack_kernel<<<(total + 255) / 256, 256>>>(W_ih0, W_ihr, W_hh, b_ih, b_hh);

    dim3 pgrid(BATCH / PG_BT, TT / PG_TS);
    for (int l = 0; l < NL; l++) {
        if (l == 0) pre_gemm3<7, 8, 3><<<pgrid, PG_TPB, pg_smem7>>>(x, l);
        else        pre_gemm3<49, 64, 6><<<pgrid, PG_TPB, pg_smem49>>>(x, l);
        lstm_rec3<<<BATCH / 8, R_TPB, R_SMEM>>>(l);
    }

    dim3 fcg(TT, BATCH / FCB);
    fc_kernel<<<fcg, FCB>>>(fc_w, fc_b, outp);
}

// round 8
// speedup vs baseline: 1.7170x; 1.7170x over previous
#include <cuda_runtime.h>

typedef unsigned long long ull;

#define Hs     49
#define G4     196
#define NL     7
#define IN0    7
#define NOUT   7
#define BATCH  1024
#define TT     512

#define GB     16            // blocks per layer
#define BB     64            // batch rows per block
#define TPB    448           // 14 warps: 7 u-warps x 2 batch-halves
#define KX     49            // x-part K (layers >= 1)
#define KT     (Hs + KX)     // 98 packed W rows
#define VP     68            // padded row stride (floats) for vv/xs

// ---------------- device scratch ------------------------------------------
__device__ float g_wcat[NL][KT][Hs][8];     // [k][u][(wi,wi,wf,wf,wg,wg,wo,wo)]
__device__ float g_biasp[NL][Hs][4];        // b_ih + b_hh, gate order i,f,g,o
__device__ float g_hx[NL][TT][Hs][BATCH];   // layer outputs, k-major per t
__device__ int   g_flag[NL][GB];            // per (layer, slice) progress

// ---------------- helpers ---------------------------------------------------
static __device__ __forceinline__ ull pack2(float lo, float hi) {
    ull r; asm("mov.b64 %0, {%1,%2};" : "=l"(r) : "f"(lo), "f"(hi)); return r;
}
static __device__ __forceinline__ void unpack2(ull v, float &lo, float &hi) {
    asm("mov.b64 {%0,%1}, %2;" : "=f"(lo), "=f"(hi) : "l"(v));
}
static __device__ __forceinline__ ull ffma2(ull a, ull b, ull c) {
    ull d; asm("fma.rn.f32x2 %0, %1, %2, %3;" : "=l"(d) : "l"(a), "l"(b), "l"(c)); return d;
}
static __device__ __forceinline__ float ex2f(float x) {
    float r; asm("ex2.approx.f32 %0, %1;" : "=f"(r) : "f"(x)); return r;
}
static __device__ __forceinline__ float rcpf(float x) {
    float r; asm("rcp.approx.f32 %0, %1;" : "=f"(r) : "f"(x)); return r;
}
#define LOG2E 1.4426950408889634f
static __device__ __forceinline__ float sigf(float x) {
    return rcpf(1.f + ex2f(-LOG2E * x));
}
static __device__ __forceinline__ float tanhf2(float x) {
    return 1.f - 2.f * rcpf(1.f + ex2f(2.f * LOG2E * x));
}
static __device__ __forceinline__ int ldacq(const int* p) {
    int v; asm volatile("ld.global.acquire.gpu.b32 %0, [%1];" : "=r"(v) : "l"(p)); return v;
}
static __device__ __forceinline__ void strel(int* p, int v) {
    asm volatile("st.global.release.gpu.b32 [%0], %1;" :: "l"(p), "r"(v));
}

// one matvec step: 4 LDS.128 + 16 FFMA2
static __device__ __forceinline__ void mstep(const float* wrow, const float* hrow,
                                             ull a0[4], ull a1[4], ull a2[4], ull a3[4]) {
    ulonglong2 W01 = *(const ulonglong2*)(wrow);        // (wi,wi),(wf,wf)
    ulonglong2 W23 = *(const ulonglong2*)(wrow + 4);    // (wg,wg),(wo,wo)
    ulonglong2 H0  = *(const ulonglong2*)(hrow);        // (h0,h1),(h2,h3)
    ulonglong2 H1  = *(const ulonglong2*)(hrow + 4);    // (h4,h5),(h6,h7)
    a0[0] = ffma2(W01.x, H0.x, a0[0]); a0[1] = ffma2(W01.x, H0.y, a0[1]);
    a0[2] = ffma2(W01.x, H1.x, a0[2]); a0[3] = ffma2(W01.x, H1.y, a0[3]);
    a1[0] = ffma2(W01.y, H0.x, a1[0]); a1[1] = ffma2(W01.y, H0.y, a1[1]);
    a1[2] = ffma2(W01.y, H1.x, a1[2]); a1[3] = ffma2(W01.y, H1.y, a1[3]);
    a2[0] = ffma2(W23.x, H0.x, a2[0]); a2[1] = ffma2(W23.x, H0.y, a2[1]);
    a2[2] = ffma2(W23.x, H1.x, a2[2]); a2[3] = ffma2(W23.x, H1.y, a2[3]);
    a3[0] = ffma2(W23.y, H0.x, a3[0]); a3[1] = ffma2(W23.y, H0.y, a3[1]);
    a3[2] = ffma2(W23.y, H1.x, a3[2]); a3[3] = ffma2(W23.y, H1.y, a3[3]);
}

// ---------------- packing ---------------------------------------------------
__global__ void pack_kernel(const float* __restrict__ W_ih0,
                            const float* __restrict__ W_ihr,
                            const float* __restrict__ W_hh,
                            const float* __restrict__ b_ih,
                            const float* __restrict__ b_hh) {
    int idx = blockIdx.x * blockDim.x + threadIdx.x;
    const int total = NL * KT * Hs;
    if (idx >= total) return;
    int l   = idx / (KT * Hs);
    int rem = idx % (KT * Hs);
    int k   = rem / Hs;
    int u   = rem % Hs;
#pragma unroll
    for (int j = 0; j < 4; j++) {
        int row = j * Hs + u;                  // torch gate order i,f,g,o
        float wv;
        if (k < Hs) {                          // recurrent part
            wv = W_hh[(l * G4 + row) * Hs + k];
        } else {                               // input part
            int kk = k - Hs;
            if (l == 0) wv = (kk < IN0) ? W_ih0[row * IN0 + kk] : 0.f;
            else        wv = W_ihr[((l - 1) * G4 + row) * Hs + kk];
        }
        g_wcat[l][k][u][2 * j]     = wv;
        g_wcat[l][k][u][2 * j + 1] = wv;
        if (k == 0)
            g_biasp[l][u][j] = b_ih[l * G4 + row] + b_hh[l * G4 + row];
    }
}

__global__ void reset_kernel() {
    int i = threadIdx.x;
    if (i < NL * GB) ((int*)g_flag)[i] = 0;
}

// ---------------- pipelined persistent LSTM ---------------------------------
#define SM_W   (KT * Hs * 8)        // 38416
#define SM_VV  (2 * Hs * VP)        // 6664
#define SM_XS  (Hs * VP)            // 3332
#define SM_BI  (Hs * 4)             // 196
#define SMEMF  (SM_W + SM_VV + SM_XS + SM_BI)
#define SMEMB  (SMEMF * 4)

__global__ __launch_bounds__(TPB, 1)
void lstm_pipe(const float* __restrict__ xin) {
    extern __shared__ float sm[];
    float* ws = sm;                  // [ktot][49][8] dup weights
    float* vv = ws + SM_W;           // [2][49][VP]  recurrent h (batch-major rows)
    float* xs = vv + SM_VV;          // [49][VP]     staged layer input
    float* bi = xs + SM_XS;          // [49][4]

    const int bid = blockIdx.x;
    const int l   = bid / GB;
    const int g   = bid % GB;
    const int bbase = g * BB;

    const int tid  = threadIdx.x;
    const int warp = tid >> 5, lane = tid & 31;
    const int wu   = warp % 7;             // u-warp
    const int half = warp / 7;             // batch half
    const int u    = (wu << 3) | (lane >> 2);
    const int bg   = lane & 3;
    const int bh   = half * 32 + bg * 8;   // batch offset within block
    const bool act = (u < Hs);
    const int  uc  = act ? u : 0;          // clamped for addressing

    const int kxt  = (l == 0) ? IN0 : KX;
    const int ktot = Hs + kxt;

    // stage weights + bias, zero vv
    const float* wsrc = &g_wcat[l][0][0][0];
    for (int i = tid; i < ktot * Hs * 8; i += TPB) ws[i] = wsrc[i];
    const float* bsrc = &g_biasp[l][0][0];
    for (int i = tid; i < SM_BI; i += TPB) bi[i] = bsrc[i];
    for (int i = tid; i < SM_VV; i += TPB) vv[i] = 0.f;
    __syncthreads();

    ull b2[4];
    {
        float4 bv = *(const float4*)(bi + uc * 4);
        b2[0] = pack2(bv.x, bv.x); b2[1] = pack2(bv.y, bv.y);
        b2[2] = pack2(bv.z, bv.z); b2[3] = pack2(bv.w, bv.w);
    }

    const int* inflag  = &g_flag[(l == 0 ? 0 : l - 1)][g];
    int*       outflag = &g_flag[l][g];
    const float* hxin  = &g_hx[(l == 0 ? 0 : l - 1)][0][0][0];
    float*       hxout = &g_hx[l][0][0][0];

    float c[8];
#pragma unroll
    for (int i = 0; i < 8; i++) c[i] = 0.f;

    for (int t = 0; t < TT; t++) {
        const int cur = t & 1, nxt = cur ^ 1;
        const float* vvc = vv + cur * Hs * VP;
        float*       vvn = vv + nxt * Hs * VP;

        // 1. wait for input of step t (all threads poll; steady-state ~free)
        if (l > 0) {
            while (ldacq(inflag) <= t) { }
        }

        // 2. issue input-tile loads into registers (latency hidden by h-part)
        float4 sv0, sv1; int d0 = -1, d1 = -1;
        float  xv0 = 0.f, xv1 = 0.f; int s0 = -1, s1 = -1;
        if (l > 0) {
            {   // slots: 49 k-rows x 16 float4
                int i = tid, k = i >> 4, q = i & 15;
                sv0 = *(const float4*)(hxin + (t * Hs + k) * BATCH + bbase + q * 4);
                d0 = k * VP + q * 4;
            }
            int i = tid + TPB;
            if (i < Hs * 16) {
                int k = i >> 4, q = i & 15;
                sv1 = *(const float4*)(hxin + (t * Hs + k) * BATCH + bbase + q * 4);
                d1 = k * VP + q * 4;
            }
        } else {
            {   // 64 b x 8 padded slots (7 valid)
                int i = tid, b = i >> 3, kk = i & 7;
                if (kk < IN0) { xv0 = xin[(bbase + b) * TT * IN0 + t * IN0 + kk]; s0 = kk * VP + b; }
            }
            int i = tid + TPB;
            if (i < BB * 8) {
                int b = i >> 3, kk = i & 7;
                if (kk < IN0) { xv1 = xin[(bbase + b) * TT * IN0 + t * IN0 + kk]; s1 = kk * VP + b; }
            }
        }

        // 3. recurrent half of the matvec (k in [0,49), from local smem h)
        ull a0[4], a1[4], a2[4], a3[4];
#pragma unroll
        for (int p = 0; p < 4; p++) { a0[p] = b2[0]; a1[p] = b2[1]; a2[p] = b2[2]; a3[p] = b2[3]; }

#pragma unroll 7
        for (int k = 0; k < Hs; k++)
            mstep(ws + (k * Hs + uc) * 8, vvc + k * VP + bh, a0, a1, a2, a3);

        // 4. commit staged input tile
        if (l > 0) {
            if (d0 >= 0) *(float4*)(xs + d0) = sv0;
            if (d1 >= 0) *(float4*)(xs + d1) = sv1;
        } else {
            if (s0 >= 0) xs[s0] = xv0;
            if (s1 >= 0) xs[s1] = xv1;
        }
        __syncthreads();                     // S1: xs ready

        // 5. input half of the matvec (k in [0,kxt), from xs)
#pragma unroll 7
        for (int k = 0; k < kxt; k++)
            mstep(ws + ((Hs + k) * Hs + uc) * 8, xs + k * VP + bh, a0, a1, a2, a3);

        // 6. cell update + stores
        if (act) {
            float hv[8];
#pragma unroll
            for (int p = 0; p < 4; p++) {
                float i0, i1, f0, f1, g0, g1, o0, o1;
                unpack2(a0[p], i0, i1);
                unpack2(a1[p], f0, f1);
                unpack2(a2[p], g0, g1);
                unpack2(a3[p], o0, o1);
                i0 = sigf(i0); f0 = sigf(f0); g0 = tanhf2(g0); o0 = sigf(o0);
                i1 = sigf(i1); f1 = sigf(f1); g1 = tanhf2(g1); o1 = sigf(o1);
                c[2 * p]     = f0 * c[2 * p]     + i0 * g0;
                c[2 * p + 1] = f1 * c[2 * p + 1] + i1 * g1;
                hv[2 * p]     = o0 * tanhf2(c[2 * p]);
                hv[2 * p + 1] = o1 * tanhf2(c[2 * p + 1]);
            }
            *(float4*)(vvn + u * VP + bh)     = make_float4(hv[0], hv[1], hv[2], hv[3]);
            *(float4*)(vvn + u * VP + bh + 4) = make_float4(hv[4], hv[5], hv[6], hv[7]);
            float* op = hxout + (t * Hs + u) * BATCH + bbase + bh;
            *(float4*)(op)     = make_float4(hv[0], hv[1], hv[2], hv[3]);
            *(float4*)(op + 4) = make_float4(hv[4], hv[5], hv[6], hv[7]);
        }
        __syncthreads();                     // S2: h(t) fully stored

        // 7. publish step t
        if (tid == 0) strel(outflag, t + 1);
    }
}

// ---------------- final FC ---------------------------------------------------
#define FCB 128
__global__ void fc_kernel(const float* __restrict__ fc_w,
                          const float* __restrict__ fc_b,
                          float* __restrict__ outp) {
    __shared__ float sw[NOUT * Hs];
    __shared__ float sb[NOUT];
    const int t   = blockIdx.x;
    const int bc  = blockIdx.y;
    const int tid = threadIdx.x;

    for (int i = tid; i < NOUT * Hs; i += FCB) sw[i] = fc_w[i];
    if (tid < NOUT) sb[tid] = fc_b[tid];
    __syncthreads();

    const int b = bc * FCB + tid;
    const float* hrow = &g_hx[NL - 1][t][0][0];
    float o[NOUT];
#pragma unroll
    for (int j = 0; j < NOUT; j++) o[j] = sb[j];
#pragma unroll 7
    for (int u = 0; u < Hs; u++) {
        float h = hrow[u * BATCH + b];
#pragma unroll
        for (int j = 0; j < NOUT; j++) o[j] += h * sw[j * Hs + u];
    }
#pragma unroll
    for (int j = 0; j < NOUT; j++)
        outp[(b * TT + t) * NOUT + j] = o[j];
}

// ---------------- launcher ---------------------------------------------------
extern "C" void kernel_launch(void* const* d_in, const int* in_sizes, int n_in,
                              void* d_out, int out_size) {
    const float* x     = (const float*)d_in[0];
    const float* W_ih0 = (const float*)d_in[1];
    const float* W_ihr = (const float*)d_in[2];
    const float* W_hh  = (const float*)d_in[3];
    const float* b_ih  = (const float*)d_in[4];
    const float* b_hh  = (const float*)d_in[5];
    const float* fc_w  = (const float*)d_in[6];
    const float* fc_b  = (const float*)d_in[7];
    float* outp = (float*)d_out;

    cudaFuncSetAttribute(lstm_pipe, cudaFuncAttributeMaxDynamicSharedMemorySize, SMEMB);

    const int total = NL * KT * Hs;
    pack_kernel<<<(total + 255) / 256, 256>>>(W_ih0, W_ihr, W_hh, b_ih, b_hh);
    reset_kernel<<<1, 128>>>();

    lstm_pipe<<<NL * GB, TPB, SMEMB>>>(x);

    dim3 fcg(TT, BATCH / FCB);
    fc_kernel<<<fcg, FCB>>>(fc_w, fc_b, outp);
}

// round 9
// speedup vs baseline: 1.7356x; 1.0109x over previous
#include <cuda_runtime.h>

typedef unsigned long long ull;

#define Hs     49
#define G4     196
#define NL     7
#define IN0    7
#define NOUT   7
#define BATCH  1024
#define TT     512

#define GB     16            // blocks per layer
#define BB     64            // batch rows per block
#define TPB    448           // 14 warps: 7 u-warps x 2 batch-halves
#define KX     49            // x-part K (layers >= 1)
#define KT     (Hs + KX)     // 98 packed W rows
#define VP     68            // padded row stride (floats) for vv/xs

// ---------------- device scratch ------------------------------------------
__device__ float g_wcat[NL][KT][Hs][8];     // [k][u][(wi,wi,wf,wf,wg,wg,wo,wo)]
__device__ float g_biasp[NL][Hs][4];        // b_ih + b_hh, gate order i,f,g,o
__device__ float g_hx[NL][TT][Hs][BATCH];   // layer outputs, k-major per t
__device__ int   g_flag[NL][GB][32];        // progress flags, 128B padded

// ---------------- helpers ---------------------------------------------------
static __device__ __forceinline__ ull pack2(float lo, float hi) {
    ull r; asm("mov.b64 %0, {%1,%2};" : "=l"(r) : "f"(lo), "f"(hi)); return r;
}
static __device__ __forceinline__ void unpack2(ull v, float &lo, float &hi) {
    asm("mov.b64 {%0,%1}, %2;" : "=f"(lo), "=f"(hi) : "l"(v));
}
static __device__ __forceinline__ ull ffma2(ull a, ull b, ull c) {
    ull d; asm("fma.rn.f32x2 %0, %1, %2, %3;" : "=l"(d) : "l"(a), "l"(b), "l"(c)); return d;
}
static __device__ __forceinline__ float tanha(float x) {
    float r; asm("tanh.approx.f32 %0, %1;" : "=f"(r) : "f"(x)); return r;
}
static __device__ __forceinline__ float sigf(float x) {
    return fmaf(0.5f, tanha(0.5f * x), 0.5f);      // 1 MUFU + 1 FFMA
}
static __device__ __forceinline__ int ldacq(const int* p) {
    int v; asm volatile("ld.global.acquire.gpu.b32 %0, [%1];" : "=r"(v) : "l"(p)); return v;
}
static __device__ __forceinline__ void strel(int* p, int v) {
    asm volatile("st.global.release.gpu.b32 [%0], %1;" :: "l"(p), "r"(v));
}

// one matvec step: 4 LDS.128 + 16 FFMA2
static __device__ __forceinline__ void mstep(const float* wrow, const float* hrow,
                                             ull a0[4], ull a1[4], ull a2[4], ull a3[4]) {
    ulonglong2 W01 = *(const ulonglong2*)(wrow);        // (wi,wi),(wf,wf)
    ulonglong2 W23 = *(const ulonglong2*)(wrow + 4);    // (wg,wg),(wo,wo)
    ulonglong2 H0  = *(const ulonglong2*)(hrow);        // (h0,h1),(h2,h3)
    ulonglong2 H1  = *(const ulonglong2*)(hrow + 4);    // (h4,h5),(h6,h7)
    a0[0] = ffma2(W01.x, H0.x, a0[0]); a0[1] = ffma2(W01.x, H0.y, a0[1]);
    a0[2] = ffma2(W01.x, H1.x, a0[2]); a0[3] = ffma2(W01.x, H1.y, a0[3]);
    a1[0] = ffma2(W01.y, H0.x, a1[0]); a1[1] = ffma2(W01.y, H0.y, a1[1]);
    a1[2] = ffma2(W01.y, H1.x, a1[2]); a1[3] = ffma2(W01.y, H1.y, a1[3]);
    a2[0] = ffma2(W23.x, H0.x, a2[0]); a2[1] = ffma2(W23.x, H0.y, a2[1]);
    a2[2] = ffma2(W23.x, H1.x, a2[2]); a2[3] = ffma2(W23.x, H1.y, a2[3]);
    a3[0] = ffma2(W23.y, H0.x, a3[0]); a3[1] = ffma2(W23.y, H0.y, a3[1]);
    a3[2] = ffma2(W23.y, H1.x, a3[2]); a3[3] = ffma2(W23.y, H1.y, a3[3]);
}

// ---------------- packing ---------------------------------------------------
__global__ void pack_kernel(const float* __restrict__ W_ih0,
                            const float* __restrict__ W_ihr,
                            const float* __restrict__ W_hh,
                            const float* __restrict__ b_ih,
                            const float* __restrict__ b_hh) {
    int idx = blockIdx.x * blockDim.x + threadIdx.x;
    const int total = NL * KT * Hs;
    if (idx >= total) return;
    int l   = idx / (KT * Hs);
    int rem = idx % (KT * Hs);
    int k   = rem / Hs;
    int u   = rem % Hs;
#pragma unroll
    for (int j = 0; j < 4; j++) {
        int row = j * Hs + u;                  // torch gate order i,f,g,o
        float wv;
        if (k < Hs) {                          // recurrent part
            wv = W_hh[(l * G4 + row) * Hs + k];
        } else {                               // input part
            int kk = k - Hs;
            if (l == 0) wv = (kk < IN0) ? W_ih0[row * IN0 + kk] : 0.f;
            else        wv = W_ihr[((l - 1) * G4 + row) * Hs + kk];
        }
        g_wcat[l][k][u][2 * j]     = wv;
        g_wcat[l][k][u][2 * j + 1] = wv;
        if (k == 0)
            g_biasp[l][u][j] = b_ih[l * G4 + row] + b_hh[l * G4 + row];
    }
}

__global__ void reset_kernel() {
    int i = blockIdx.x * blockDim.x + threadIdx.x;
    if (i < NL * GB * 32) ((int*)g_flag)[i] = 0;
}

// ---------------- pipelined persistent LSTM ---------------------------------
#define SM_W   (KT * Hs * 8)        // 38416
#define SM_VV  (2 * Hs * VP)        // 6664
#define SM_XS  (Hs * VP)            // 3332
#define SM_BI  (Hs * 4)             // 196
#define SMEMF  (SM_W + SM_VV + SM_XS + SM_BI)
#define SMEMB  (SMEMF * 4)

__global__ __launch_bounds__(TPB, 1)
void lstm_pipe(const float* __restrict__ xin) {
    extern __shared__ float sm[];
    float* ws = sm;                  // [ktot][49][8] dup weights
    float* vv = ws + SM_W;           // [2][49][VP]  recurrent h (batch-major rows)
    float* xs = vv + SM_VV;          // [49][VP]     staged layer input
    float* bi = xs + SM_XS;          // [49][4]

    const int bid = blockIdx.x;
    const int l   = bid / GB;
    const int g   = bid % GB;
    const int bbase = g * BB;

    const int tid  = threadIdx.x;
    const int warp = tid >> 5, lane = tid & 31;
    const int wu   = warp % 7;             // u-warp
    const int half = warp / 7;             // batch half
    const int u    = (wu << 3) | (lane >> 2);
    const int bg   = lane & 3;
    const int bh   = half * 32 + bg * 8;   // batch offset within block
    const bool act = (u < Hs);
    const int  uc  = act ? u : 0;          // clamped for addressing

    const int kxt  = (l == 0) ? IN0 : KX;
    const int ktot = Hs + kxt;

    // stage weights + bias, zero vv
    const float* wsrc = &g_wcat[l][0][0][0];
    for (int i = tid; i < ktot * Hs * 8; i += TPB) ws[i] = wsrc[i];
    const float* bsrc = &g_biasp[l][0][0];
    for (int i = tid; i < SM_BI; i += TPB) bi[i] = bsrc[i];
    for (int i = tid; i < SM_VV; i += TPB) vv[i] = 0.f;
    __syncthreads();

    ull b2[4];
    {
        float4 bv = *(const float4*)(bi + uc * 4);
        b2[0] = pack2(bv.x, bv.x); b2[1] = pack2(bv.y, bv.y);
        b2[2] = pack2(bv.z, bv.z); b2[3] = pack2(bv.w, bv.w);
    }

    const int* inflag  = &g_flag[(l == 0 ? 0 : l - 1)][g][0];
    int*       outflag = &g_flag[l][g][0];
    const float* hxin  = &g_hx[(l == 0 ? 0 : l - 1)][0][0][0];
    float*       hxout = &g_hx[l][0][0][0];

    float c[8];
#pragma unroll
    for (int i = 0; i < 8; i++) c[i] = 0.f;

    for (int t = 0; t < TT; t++) {
        const int cur = t & 1, nxt = cur ^ 1;
        const float* vvc = vv + cur * Hs * VP;
        float*       vvn = vv + nxt * Hs * VP;

        // 1. tid0 waits for input of step t (backoff poll — no L2 spin storm)
        if (l > 0) {
            if (tid == 0) {
                while (ldacq(inflag) <= t) __nanosleep(64);
            }
            __syncthreads();
        }

        // 2. issue input-tile loads into registers (latency hidden by h-part)
        float4 sv0, sv1; int d0 = -1, d1 = -1;
        float  xv0 = 0.f, xv1 = 0.f; int s0 = -1, s1 = -1;
        if (l > 0) {
            {   // slots: 49 k-rows x 16 float4
                int i = tid, k = i >> 4, q = i & 15;
                sv0 = *(const float4*)(hxin + (t * Hs + k) * BATCH + bbase + q * 4);
                d0 = k * VP + q * 4;
            }
            int i = tid + TPB;
            if (i < Hs * 16) {
                int k = i >> 4, q = i & 15;
                sv1 = *(const float4*)(hxin + (t * Hs + k) * BATCH + bbase + q * 4);
                d1 = k * VP + q * 4;
            }
        } else {
            {   // 64 b x 8 padded slots (7 valid)
                int i = tid, b = i >> 3, kk = i & 7;
                if (kk < IN0) { xv0 = xin[(bbase + b) * TT * IN0 + t * IN0 + kk]; s0 = kk * VP + b; }
            }
            int i = tid + TPB;
            if (i < BB * 8) {
                int b = i >> 3, kk = i & 7;
                if (kk < IN0) { xv1 = xin[(bbase + b) * TT * IN0 + t * IN0 + kk]; s1 = kk * VP + b; }
            }
        }

        // 3. recurrent half of the matvec (k in [0,49), from local smem h)
        ull a0[4], a1[4], a2[4], a3[4];
#pragma unroll
        for (int p = 0; p < 4; p++) { a0[p] = b2[0]; a1[p] = b2[1]; a2[p] = b2[2]; a3[p] = b2[3]; }

#pragma unroll 7
        for (int k = 0; k < Hs; k++)
            mstep(ws + (k * Hs + uc) * 8, vvc + k * VP + bh, a0, a1, a2, a3);

        // 4. commit staged input tile
        if (l > 0) {
            if (d0 >= 0) *(float4*)(xs + d0) = sv0;
            if (d1 >= 0) *(float4*)(xs + d1) = sv1;
        } else {
            if (s0 >= 0) xs[s0] = xv0;
            if (s1 >= 0) xs[s1] = xv1;
        }
        __syncthreads();                     // S1: xs ready

        // 5. input half of the matvec (k in [0,kxt), from xs)
#pragma unroll 7
        for (int k = 0; k < kxt; k++)
            mstep(ws + ((Hs + k) * Hs + uc) * 8, xs + k * VP + bh, a0, a1, a2, a3);

        // 6. cell update + stores (MUFU.TANH epilogue)
        if (act) {
            float hv[8];
#pragma unroll
            for (int p = 0; p < 4; p++) {
                float i0, i1, f0, f1, g0, g1, o0, o1;
                unpack2(a0[p], i0, i1);
                unpack2(a1[p], f0, f1);
                unpack2(a2[p], g0, g1);
                unpack2(a3[p], o0, o1);
                i0 = sigf(i0); f0 = sigf(f0); g0 = tanha(g0); o0 = sigf(o0);
                i1 = sigf(i1); f1 = sigf(f1); g1 = tanha(g1); o1 = sigf(o1);
                c[2 * p]     = f0 * c[2 * p]     + i0 * g0;
                c[2 * p + 1] = f1 * c[2 * p + 1] + i1 * g1;
                hv[2 * p]     = o0 * tanha(c[2 * p]);
                hv[2 * p + 1] = o1 * tanha(c[2 * p + 1]);
            }
            *(float4*)(vvn + u * VP + bh)     = make_float4(hv[0], hv[1], hv[2], hv[3]);
            *(float4*)(vvn + u * VP + bh + 4) = make_float4(hv[4], hv[5], hv[6], hv[7]);
            float* op = hxout + (t * Hs + u) * BATCH + bbase + bh;
            *(float4*)(op)     = make_float4(hv[0], hv[1], hv[2], hv[3]);
            *(float4*)(op + 4) = make_float4(hv[4], hv[5], hv[6], hv[7]);
        }
        __syncthreads();                     // S2: h(t) fully stored

        // 7. publish step t
        if (tid == 0) strel(outflag, t + 1);
    }
}

// ---------------- final FC ---------------------------------------------------
#define FCB 128
__global__ void fc_kernel(const float* __restrict__ fc_w,
                          const float* __restrict__ fc_b,
                          float* __restrict__ outp) {
    __shared__ float sw[NOUT * Hs];
    __shared__ float sb[NOUT];
    const int t   = blockIdx.x;
    const int bc  = blockIdx.y;
    const int tid = threadIdx.x;

    for (int i = tid; i < NOUT * Hs; i += FCB) sw[i] = fc_w[i];
    if (tid < NOUT) sb[tid] = fc_b[tid];
    __syncthreads();

    const int b = bc * FCB + tid;
    const float* hrow = &g_hx[NL - 1][t][0][0];
    float o[NOUT];
#pragma unroll
    for (int j = 0; j < NOUT; j++) o[j] = sb[j];
#pragma unroll 7
    for (int u = 0; u < Hs; u++) {
        float h = hrow[u * BATCH + b];
#pragma unroll
        for (int j = 0; j < NOUT; j++) o[j] += h * sw[j * Hs + u];
    }
#pragma unroll
    for (int j = 0; j < NOUT; j++)
        outp[(b * TT + t) * NOUT + j] = o[j];
}

// ---------------- launcher ---------------------------------------------------
extern "C" void kernel_launch(void* const* d_in, const int* in_sizes, int n_in,
                              void* d_out, int out_size) {
    const float* x     = (const float*)d_in[0];
    const float* W_ih0 = (const float*)d_in[1];
    const float* W_ihr = (const float*)d_in[2];
    const float* W_hh  = (const float*)d_in[3];
    const float* b_ih  = (const float*)d_in[4];
    const float* b_hh  = (const float*)d_in[5];
    const float* fc_w  = (const float*)d_in[6];
    const float* fc_b  = (const float*)d_in[7];
    float* outp = (float*)d_out;

    cudaFuncSetAttribute(lstm_pipe, cudaFuncAttributeMaxDynamicSharedMemorySize, SMEMB);

    const int total = NL * KT * Hs;
    pack_kernel<<<(total + 255) / 256, 256>>>(W_ih0, W_ihr, W_hh, b_ih, b_hh);
    reset_kernel<<<(NL * GB * 32 + 127) / 128, 128>>>();

    lstm_pipe<<<NL * GB, TPB, SMEMB>>>(x);

    dim3 fcg(TT, BATCH / FCB);
    fc_kernel<<<fcg, FCB>>>(fc_w, fc_b, outp);
}

// round 10
// speedup vs baseline: 1.8022x; 1.0384x over previous
#include <cuda_runtime.h>

typedef unsigned long long ull;

#define Hs     49
#define G4     196
#define NL     7
#define IN0    7
#define NOUT   7
#define BATCH  1024
#define TT     512

#define GB     16            // blocks per layer
#define BB     64            // batch rows per block
#define TPB    448           // 14 warps: 7 u-warps x 2 batch-halves
#define KX     49            // x-part K (layers >= 1)
#define KT     (Hs + KX)     // 98 packed W rows
#define VP     68            // padded row stride (floats) for vv/xs

// ---------------- device scratch ------------------------------------------
__device__ float g_wcat[NL][KT][Hs][8];     // [k][u][(wi,wi,wf,wf,wg,wg,wo,wo)]
__device__ float g_biasp[NL][Hs][4];        // b_ih + b_hh, gate order i,f,g,o
__device__ float g_hx[NL][TT][Hs][BATCH];   // layer outputs, k-major per t
__device__ int   g_flag[NL][GB][32];        // progress flags, 128B padded

// ---------------- helpers ---------------------------------------------------
static __device__ __forceinline__ ull pack2(float lo, float hi) {
    ull r; asm("mov.b64 %0, {%1,%2};" : "=l"(r) : "f"(lo), "f"(hi)); return r;
}
static __device__ __forceinline__ void unpack2(ull v, float &lo, float &hi) {
    asm("mov.b64 {%0,%1}, %2;" : "=f"(lo), "=f"(hi) : "l"(v));
}
static __device__ __forceinline__ ull ffma2(ull a, ull b, ull c) {
    ull d; asm("fma.rn.f32x2 %0, %1, %2, %3;" : "=l"(d) : "l"(a), "l"(b), "l"(c)); return d;
}
static __device__ __forceinline__ float tanha(float x) {
    float r; asm("tanh.approx.f32 %0, %1;" : "=f"(r) : "f"(x)); return r;
}
static __device__ __forceinline__ float sigf(float x) {
    return fmaf(0.5f, tanha(0.5f * x), 0.5f);      // 1 MUFU + 1 FFMA
}
static __device__ __forceinline__ int ldacq(const int* p) {
    int v; asm volatile("ld.global.acquire.gpu.b32 %0, [%1];" : "=r"(v) : "l"(p)); return v;
}
static __device__ __forceinline__ void strel(int* p, int v) {
    asm volatile("st.global.release.gpu.b32 [%0], %1;" :: "l"(p), "r"(v));
}

// one matvec step: 4 LDS.128 + 16 FFMA2
static __device__ __forceinline__ void mstep(const float* wrow, const float* hrow,
                                             ull a0[4], ull a1[4], ull a2[4], ull a3[4]) {
    ulonglong2 W01 = *(const ulonglong2*)(wrow);        // (wi,wi),(wf,wf)
    ulonglong2 W23 = *(const ulonglong2*)(wrow + 4);    // (wg,wg),(wo,wo)
    ulonglong2 H0  = *(const ulonglong2*)(hrow);        // (h0,h1),(h2,h3)
    ulonglong2 H1  = *(const ulonglong2*)(hrow + 4);    // (h4,h5),(h6,h7)
    a0[0] = ffma2(W01.x, H0.x, a0[0]); a0[1] = ffma2(W01.x, H0.y, a0[1]);
    a0[2] = ffma2(W01.x, H1.x, a0[2]); a0[3] = ffma2(W01.x, H1.y, a0[3]);
    a1[0] = ffma2(W01.y, H0.x, a1[0]); a1[1] = ffma2(W01.y, H0.y, a1[1]);
    a1[2] = ffma2(W01.y, H1.x, a1[2]); a1[3] = ffma2(W01.y, H1.y, a1[3]);
    a2[0] = ffma2(W23.x, H0.x, a2[0]); a2[1] = ffma2(W23.x, H0.y, a2[1]);
    a2[2] = ffma2(W23.x, H1.x, a2[2]); a2[3] = ffma2(W23.x, H1.y, a2[3]);
    a3[0] = ffma2(W23.y, H0.x, a3[0]); a3[1] = ffma2(W23.y, H0.y, a3[1]);
    a3[2] = ffma2(W23.y, H1.x, a3[2]); a3[3] = ffma2(W23.y, H1.y, a3[3]);
}

// ---------------- packing ---------------------------------------------------
__global__ void pack_kernel(const float* __restrict__ W_ih0,
                            const float* __restrict__ W_ihr,
                            const float* __restrict__ W_hh,
                            const float* __restrict__ b_ih,
                            const float* __restrict__ b_hh) {
    int idx = blockIdx.x * blockDim.x + threadIdx.x;
    const int total = NL * KT * Hs;
    if (idx >= total) return;
    int l   = idx / (KT * Hs);
    int rem = idx % (KT * Hs);
    int k   = rem / Hs;
    int u   = rem % Hs;
#pragma unroll
    for (int j = 0; j < 4; j++) {
        int row = j * Hs + u;                  // torch gate order i,f,g,o
        float wv;
        if (k < Hs) {                          // recurrent part
            wv = W_hh[(l * G4 + row) * Hs + k];
        } else {                               // input part
            int kk = k - Hs;
            if (l == 0) wv = (kk < IN0) ? W_ih0[row * IN0 + kk] : 0.f;
            else        wv = W_ihr[((l - 1) * G4 + row) * Hs + kk];
        }
        g_wcat[l][k][u][2 * j]     = wv;
        g_wcat[l][k][u][2 * j + 1] = wv;
        if (k == 0)
            g_biasp[l][u][j] = b_ih[l * G4 + row] + b_hh[l * G4 + row];
    }
}

__global__ void reset_kernel() {
    int i = blockIdx.x * blockDim.x + threadIdx.x;
    if (i < NL * GB * 32) ((int*)g_flag)[i] = 0;
}

// ---------------- pipelined persistent LSTM ---------------------------------
#define SM_W   (KT * Hs * 8)        // 38416
#define SM_VV  (2 * Hs * VP)        // 6664
#define SM_XS  (2 * Hs * VP)        // 6664 (double-buffered input tile)
#define SM_BI  (Hs * 4)             // 196
#define SMEMF  (SM_W + SM_VV + SM_XS + SM_BI)
#define SMEMB  (SMEMF * 4)          // 207,760 B

__global__ __launch_bounds__(TPB, 1)
void lstm_pipe(const float* __restrict__ xin) {
    extern __shared__ float sm[];
    float* ws = sm;                  // [ktot][49][8] dup weights
    float* vv = ws + SM_W;           // [2][49][VP]  recurrent h
    float* xs = vv + SM_VV;          // [2][49][VP]  staged layer input
    float* bi = xs + SM_XS;          // [49][4]

    const int bid = blockIdx.x;
    const int l   = bid / GB;
    const int g   = bid % GB;
    const int bbase = g * BB;

    const int tid  = threadIdx.x;
    const int warp = tid >> 5, lane = tid & 31;
    const int wu   = warp % 7;             // u-warp
    const int half = warp / 7;             // batch half
    const int u    = (wu << 3) | (lane >> 2);
    const int bg   = lane & 3;
    const int bh   = half * 32 + bg * 8;   // batch offset within block
    const bool act = (u < Hs);
    const int  uc  = act ? u : 0;

    const int kxt  = (l == 0) ? IN0 : KX;
    const int ktot = Hs + kxt;

    // stage weights + bias, zero vv
    const float* wsrc = &g_wcat[l][0][0][0];
    for (int i = tid; i < ktot * Hs * 8; i += TPB) ws[i] = wsrc[i];
    const float* bsrc = &g_biasp[l][0][0];
    for (int i = tid; i < SM_BI; i += TPB) bi[i] = bsrc[i];
    for (int i = tid; i < SM_VV; i += TPB) vv[i] = 0.f;

    const int* inflag  = &g_flag[(l == 0 ? 0 : l - 1)][g][0];
    int*       outflag = &g_flag[l][g][0];
    const float* hxin  = &g_hx[(l == 0 ? 0 : l - 1)][0][0][0];
    float*       hxout = &g_hx[l][0][0][0];

    // per-thread load slots (t-invariant)
    int k0 = 0, q0 = 0, k1 = 0, q1 = 0;       // l > 0 slots
    bool v1 = false;
    int xb0 = 0, xk0 = 0, xb1 = 0, xk1 = 0;   // l == 0 slots
    bool xv0ok = false, xv1ok = false;
    if (l > 0) {
        k0 = tid >> 4;  q0 = tid & 15;
        int i = tid + TPB;
        v1 = (i < Hs * 16);
        k1 = i >> 4;    q1 = i & 15;
        if (!v1) { k1 = 0; q1 = 0; }
    } else {
        xb0 = tid >> 3;  xk0 = tid & 7;  xv0ok = (xk0 < IN0);
        int i = tid + TPB;
        xv1ok = (i < BB * 8) && ((i & 7) < IN0);
        xb1 = i >> 3;    xk1 = i & 7;
        if (i >= BB * 8) { xb1 = 0; xk1 = 0; }
    }

    // ---- stage xs[0] for t = 0 ----
    if (l > 0) {
        if (tid == 0) { while (ldacq(inflag) < 1) __nanosleep(128); }
        __syncthreads();   // also covers ws/vv staging
        {
            float4 s = *(const float4*)(hxin + (0 * Hs + k0) * BATCH + bbase + q0 * 4);
            *(float4*)(xs + k0 * VP + q0 * 4) = s;
        }
        if (v1) {
            float4 s = *(const float4*)(hxin + (0 * Hs + k1) * BATCH + bbase + q1 * 4);
            *(float4*)(xs + k1 * VP + q1 * 4) = s;
        }
    } else {
        if (xv0ok) xs[xk0 * VP + xb0] = xin[(bbase + xb0) * TT * IN0 + 0 * IN0 + xk0];
        if (xv1ok) xs[xk1 * VP + xb1] = xin[(bbase + xb1) * TT * IN0 + 0 * IN0 + xk1];
    }
    __syncthreads();

    ull b2[4];
    {
        float4 bv = *(const float4*)(bi + uc * 4);
        b2[0] = pack2(bv.x, bv.x); b2[1] = pack2(bv.y, bv.y);
        b2[2] = pack2(bv.z, bv.z); b2[3] = pack2(bv.w, bv.w);
    }

    float c[8];
#pragma unroll
    for (int i = 0; i < 8; i++) c[i] = 0.f;

    for (int t = 0; t < TT; t++) {
        const int cur = t & 1, nxt = cur ^ 1;
        const float* vvc = vv + cur * Hs * VP;
        float*       vvn = vv + nxt * Hs * VP;
        const float* xsc = xs + cur * Hs * VP;
        float*       xsn = xs + nxt * Hs * VP;

        // 1. prefetch input tile for t+1 into registers (one-pass poll; the
        //    LDG latency is hidden under the full matvec below)
        float4 sv0, sv1;
        float  xv0 = 0.f, xv1 = 0.f;
        const bool pf = (t + 1 < TT);
        if (pf) {
            if (l > 0) {
                while (ldacq(inflag) < t + 2) __nanosleep(128);
                sv0 = *(const float4*)(hxin + ((t + 1) * Hs + k0) * BATCH + bbase + q0 * 4);
                if (v1)
                    sv1 = *(const float4*)(hxin + ((t + 1) * Hs + k1) * BATCH + bbase + q1 * 4);
            } else {
                if (xv0ok) xv0 = xin[(bbase + xb0) * TT * IN0 + (t + 1) * IN0 + xk0];
                if (xv1ok) xv1 = xin[(bbase + xb1) * TT * IN0 + (t + 1) * IN0 + xk1];
            }
        }

        // 2. full matvec: recurrent part (vv) then input part (xs), no barrier
        ull a0[4], a1[4], a2[4], a3[4];
#pragma unroll
        for (int p = 0; p < 4; p++) { a0[p] = b2[0]; a1[p] = b2[1]; a2[p] = b2[2]; a3[p] = b2[3]; }

#pragma unroll 7
        for (int k = 0; k < Hs; k++)
            mstep(ws + (k * Hs + uc) * 8, vvc + k * VP + bh, a0, a1, a2, a3);
#pragma unroll 7
        for (int k = 0; k < kxt; k++)
            mstep(ws + ((Hs + k) * Hs + uc) * 8, xsc + k * VP + bh, a0, a1, a2, a3);

        // 3. cell update + stores
        if (act) {
            float hv[8];
#pragma unroll
            for (int p = 0; p < 4; p++) {
                float i0, i1, f0, f1, g0, g1, o0, o1;
                unpack2(a0[p], i0, i1);
                unpack2(a1[p], f0, f1);
                unpack2(a2[p], g0, g1);
                unpack2(a3[p], o0, o1);
                i0 = sigf(i0); f0 = sigf(f0); g0 = tanha(g0); o0 = sigf(o0);
                i1 = sigf(i1); f1 = sigf(f1); g1 = tanha(g1); o1 = sigf(o1);
                c[2 * p]     = f0 * c[2 * p]     + i0 * g0;
                c[2 * p + 1] = f1 * c[2 * p + 1] + i1 * g1;
                hv[2 * p]     = o0 * tanha(c[2 * p]);
                hv[2 * p + 1] = o1 * tanha(c[2 * p + 1]);
            }
            float* op = hxout + (t * Hs + u) * BATCH + bbase + bh;
            *(float4*)(op)     = make_float4(hv[0], hv[1], hv[2], hv[3]);
            *(float4*)(op + 4) = make_float4(hv[4], hv[5], hv[6], hv[7]);
            *(float4*)(vvn + u * VP + bh)     = make_float4(hv[0], hv[1], hv[2], hv[3]);
            *(float4*)(vvn + u * VP + bh + 4) = make_float4(hv[4], hv[5], hv[6], hv[7]);
        }

        // 4. commit prefetched tile into xs[nxt]
        if (pf) {
            if (l > 0) {
                *(float4*)(xsn + k0 * VP + q0 * 4) = sv0;
                if (v1) *(float4*)(xsn + k1 * VP + q1 * 4) = sv1;
            } else {
                if (xv0ok) xsn[xk0 * VP + xb0] = xv0;
                if (xv1ok) xsn[xk1 * VP + xb1] = xv1;
            }
        }
        __syncthreads();                     // single barrier per step

        // 5. publish step t (h(t) stores drained by the barrier)
        if (tid == 0) strel(outflag, t + 1);
    }
}

// ---------------- final FC ---------------------------------------------------
#define FCB 128
__global__ void fc_kernel(const float* __restrict__ fc_w,
                          const float* __restrict__ fc_b,
                          float* __restrict__ outp) {
    __shared__ float sw[NOUT * Hs];
    __shared__ float sb[NOUT];
    const int t   = blockIdx.x;
    const int bc  = blockIdx.y;
    const int tid = threadIdx.x;

    for (int i = tid; i < NOUT * Hs; i += FCB) sw[i] = fc_w[i];
    if (tid < NOUT) sb[tid] = fc_b[tid];
    __syncthreads();

    const int b = bc * FCB + tid;
    const float* hrow = &g_hx[NL - 1][t][0][0];
    float o[NOUT];
#pragma unroll
    for (int j = 0; j < NOUT; j++) o[j] = sb[j];
#pragma unroll 7
    for (int u = 0; u < Hs; u++) {
        float h = hrow[u * BATCH + b];
#pragma unroll
        for (int j = 0; j < NOUT; j++) o[j] += h * sw[j * Hs + u];
    }
#pragma unroll
    for (int j = 0; j < NOUT; j++)
        outp[(b * TT + t) * NOUT + j] = o[j];
}

// ---------------- launcher ---------------------------------------------------
extern "C" void kernel_launch(void* const* d_in, const int* in_sizes, int n_in,
                              void* d_out, int out_size) {
    const float* x     = (const float*)d_in[0];
    const float* W_ih0 = (const float*)d_in[1];
    const float* W_ihr = (const float*)d_in[2];
    const float* W_hh  = (const float*)d_in[3];
    const float* b_ih  = (const float*)d_in[4];
    const float* b_hh  = (const float*)d_in[5];
    const float* fc_w  = (const float*)d_in[6];
    const float* fc_b  = (const float*)d_in[7];
    float* outp = (float*)d_out;

    cudaFuncSetAttribute(lstm_pipe, cudaFuncAttributeMaxDynamicSharedMemorySize, SMEMB);

    const int total = NL * KT * Hs;
    pack_kernel<<<(total + 255) / 256, 256>>>(W_ih0, W_ihr, W_hh, b_ih, b_hh);
    reset_kernel<<<(NL * GB * 32 + 127) / 128, 128>>>();

    lstm_pipe<<<NL * GB, TPB, SMEMB>>>(x);

    dim3 fcg(TT, BATCH / FCB);
    fc_kernel<<<fcg, FCB>>>(fc_w, fc_b, outp);
}

// round 11
// speedup vs baseline: 1.8069x; 1.0026x over previous
#include <cuda_runtime.h>

typedef unsigned long long ull;

#define Hs     49
#define G4     196
#define NL     7
#define IN0    7
#define NOUT   7
#define BATCH  1024
#define TT     512

#define GB     16            // blocks per layer
#define BB     64            // batch rows per block
#define TPB    448           // 14 warps: 7 u-warps x 2 batch-halves
#define KX     49            // x-part K (layers >= 1)
#define KT     (Hs + KX)     // 98 packed W rows
#define VP     68            // padded row stride (floats) for vv/xs

// ---------------- device scratch ------------------------------------------
__device__ float g_wcat[NL][KT][Hs][8];     // [k][u][(wi,wi,wf,wf,wg,wg,wo,wo)]
__device__ float g_biasp[NL][Hs][4];        // b_ih + b_hh, gate order i,f,g,o
__device__ float g_hx[NL][TT][Hs][BATCH];   // layer outputs, k-major per t
__device__ int   g_flag[NL][GB][32];        // progress flags, 128B padded

// ---------------- helpers ---------------------------------------------------
static __device__ __forceinline__ ull pack2(float lo, float hi) {
    ull r; asm("mov.b64 %0, {%1,%2};" : "=l"(r) : "f"(lo), "f"(hi)); return r;
}
static __device__ __forceinline__ void unpack2(ull v, float &lo, float &hi) {
    asm("mov.b64 {%0,%1}, %2;" : "=f"(lo), "=f"(hi) : "l"(v));
}
static __device__ __forceinline__ ull ffma2(ull a, ull b, ull c) {
    ull d; asm("fma.rn.f32x2 %0, %1, %2, %3;" : "=l"(d) : "l"(a), "l"(b), "l"(c)); return d;
}
static __device__ __forceinline__ float tanha(float x) {
    float r; asm("tanh.approx.f32 %0, %1;" : "=f"(r) : "f"(x)); return r;
}
static __device__ __forceinline__ float sigf(float x) {
    return fmaf(0.5f, tanha(0.5f * x), 0.5f);      // 1 MUFU + 1 FFMA
}
static __device__ __forceinline__ int ldacq(const int* p) {
    int v; asm volatile("ld.global.acquire.gpu.b32 %0, [%1];" : "=r"(v) : "l"(p)); return v;
}
static __device__ __forceinline__ void strel(int* p, int v) {
    asm volatile("st.global.release.gpu.b32 [%0], %1;" :: "l"(p), "r"(v));
}

// one matvec step: 4 LDS.128 + 16 FFMA2
static __device__ __forceinline__ void mstep(const float* wrow, const float* hrow,
                                             ull a0[4], ull a1[4], ull a2[4], ull a3[4]) {
    ulonglong2 W01 = *(const ulonglong2*)(wrow);        // (wi,wi),(wf,wf)
    ulonglong2 W23 = *(const ulonglong2*)(wrow + 4);    // (wg,wg),(wo,wo)
    ulonglong2 H0  = *(const ulonglong2*)(hrow);        // (h0,h1),(h2,h3)
    ulonglong2 H1  = *(const ulonglong2*)(hrow + 4);    // (h4,h5),(h6,h7)
    a0[0] = ffma2(W01.x, H0.x, a0[0]); a0[1] = ffma2(W01.x, H0.y, a0[1]);
    a0[2] = ffma2(W01.x, H1.x, a0[2]); a0[3] = ffma2(W01.x, H1.y, a0[3]);
    a1[0] = ffma2(W01.y, H0.x, a1[0]); a1[1] = ffma2(W01.y, H0.y, a1[1]);
    a1[2] = ffma2(W01.y, H1.x, a1[2]); a1[3] = ffma2(W01.y, H1.y, a1[3]);
    a2[0] = ffma2(W23.x, H0.x, a2[0]); a2[1] = ffma2(W23.x, H0.y, a2[1]);
    a2[2] = ffma2(W23.x, H1.x, a2[2]); a2[3] = ffma2(W23.x, H1.y, a2[3]);
    a3[0] = ffma2(W23.y, H0.x, a3[0]); a3[1] = ffma2(W23.y, H0.y, a3[1]);
    a3[2] = ffma2(W23.y, H1.x, a3[2]); a3[3] = ffma2(W23.y, H1.y, a3[3]);
}

// ---------------- packing ---------------------------------------------------
__global__ void pack_kernel(const float* __restrict__ W_ih0,
                            const float* __restrict__ W_ihr,
                            const float* __restrict__ W_hh,
                            const float* __restrict__ b_ih,
                            const float* __restrict__ b_hh) {
    int idx = blockIdx.x * blockDim.x + threadIdx.x;
    const int total = NL * KT * Hs;
    if (idx >= total) return;
    int l   = idx / (KT * Hs);
    int rem = idx % (KT * Hs);
    int k   = rem / Hs;
    int u   = rem % Hs;
#pragma unroll
    for (int j = 0; j < 4; j++) {
        int row = j * Hs + u;                  // torch gate order i,f,g,o
        float wv;
        if (k < Hs) {                          // recurrent part
            wv = W_hh[(l * G4 + row) * Hs + k];
        } else {                               // input part
            int kk = k - Hs;
            if (l == 0) wv = (kk < IN0) ? W_ih0[row * IN0 + kk] : 0.f;
            else        wv = W_ihr[((l - 1) * G4 + row) * Hs + kk];
        }
        g_wcat[l][k][u][2 * j]     = wv;
        g_wcat[l][k][u][2 * j + 1] = wv;
        if (k == 0)
            g_biasp[l][u][j] = b_ih[l * G4 + row] + b_hh[l * G4 + row];
    }
}

__global__ void reset_kernel() {
    int i = blockIdx.x * blockDim.x + threadIdx.x;
    if (i < NL * GB * 32) ((int*)g_flag)[i] = 0;
}

// ---------------- pipelined persistent LSTM ---------------------------------
#define SM_W   (KT * Hs * 8)        // 38416
#define SM_VV  (2 * Hs * VP)        // 6664
#define SM_XS  (2 * Hs * VP)        // 6664 (double-buffered input tile)
#define SM_BI  (Hs * 4)             // 196
#define SMEMF  (SM_W + SM_VV + SM_XS + SM_BI)
#define SMEMB  (SMEMF * 4)          // 207,760 B

__global__ __launch_bounds__(TPB, 1)
void lstm_pipe(const float* __restrict__ xin) {
    extern __shared__ float sm[];
    float* ws = sm;                  // [ktot][49][8] dup weights
    float* vv = ws + SM_W;           // [2][49][VP]  recurrent h
    float* xs = vv + SM_VV;          // [2][49][VP]  staged layer input
    float* bi = xs + SM_XS;          // [49][4]

    const int bid = blockIdx.x;
    const int l   = bid / GB;
    const int g   = bid % GB;
    const int bbase = g * BB;

    const int tid  = threadIdx.x;
    const int warp = tid >> 5, lane = tid & 31;
    const int wu   = warp % 7;             // u-warp
    const int half = warp / 7;             // batch half
    const int u    = (wu << 3) | (lane >> 2);
    const int bg   = lane & 3;
    const int bh   = half * 32 + bg * 8;   // batch offset within block
    const bool act = (u < Hs);
    const int  uc  = act ? u : 0;

    const int kxt  = (l == 0) ? IN0 : KX;
    const int ktot = Hs + kxt;

    // stage weights + bias, zero vv
    const float* wsrc = &g_wcat[l][0][0][0];
    for (int i = tid; i < ktot * Hs * 8; i += TPB) ws[i] = wsrc[i];
    const float* bsrc = &g_biasp[l][0][0];
    for (int i = tid; i < SM_BI; i += TPB) bi[i] = bsrc[i];
    for (int i = tid; i < SM_VV; i += TPB) vv[i] = 0.f;

    const int* inflag  = &g_flag[(l == 0 ? 0 : l - 1)][g][0];
    int*       outflag = &g_flag[l][g][0];
    const float* hxin  = &g_hx[(l == 0 ? 0 : l - 1)][0][0][0];
    float*       hxout = &g_hx[l][0][0][0];

    // per-thread load slots (t-invariant)
    int k0 = 0, q0 = 0, k1 = 0, q1 = 0;       // l > 0 slots
    bool v1 = false;
    int xb0 = 0, xk0 = 0, xb1 = 0, xk1 = 0;   // l == 0 slots
    bool xv0ok = false, xv1ok = false;
    if (l > 0) {
        k0 = tid >> 4;  q0 = tid & 15;
        int i = tid + TPB;
        v1 = (i < Hs * 16);
        k1 = i >> 4;    q1 = i & 15;
        if (!v1) { k1 = 0; q1 = 0; }
    } else {
        xb0 = tid >> 3;  xk0 = tid & 7;  xv0ok = (xk0 < IN0);
        int i = tid + TPB;
        xv1ok = (i < BB * 8) && ((i & 7) < IN0);
        xb1 = i >> 3;    xk1 = i & 7;
        if (i >= BB * 8) { xb1 = 0; xk1 = 0; }
    }

    // ---- stage xs[0] for t = 0 ----
    if (l > 0) {
        if (tid == 0) { while (ldacq(inflag) < 1) __nanosleep(128); }
        __syncthreads();   // also covers ws/vv staging
        {
            float4 s = *(const float4*)(hxin + (0 * Hs + k0) * BATCH + bbase + q0 * 4);
            *(float4*)(xs + k0 * VP + q0 * 4) = s;
        }
        if (v1) {
            float4 s = *(const float4*)(hxin + (0 * Hs + k1) * BATCH + bbase + q1 * 4);
            *(float4*)(xs + k1 * VP + q1 * 4) = s;
        }
    } else {
        if (xv0ok) xs[xk0 * VP + xb0] = xin[(bbase + xb0) * TT * IN0 + 0 * IN0 + xk0];
        if (xv1ok) xs[xk1 * VP + xb1] = xin[(bbase + xb1) * TT * IN0 + 0 * IN0 + xk1];
    }
    __syncthreads();

    ull b2[4];
    {
        float4 bv = *(const float4*)(bi + uc * 4);
        b2[0] = pack2(bv.x, bv.x); b2[1] = pack2(bv.y, bv.y);
        b2[2] = pack2(bv.z, bv.z); b2[3] = pack2(bv.w, bv.w);
    }

    float c[8];
#pragma unroll
    for (int i = 0; i < 8; i++) c[i] = 0.f;

    for (int t = 0; t < TT; t++) {
        const int cur = t & 1, nxt = cur ^ 1;
        const float* vvc = vv + cur * Hs * VP;
        float*       vvn = vv + nxt * Hs * VP;
        const float* xsc = xs + cur * Hs * VP;
        float*       xsn = xs + nxt * Hs * VP;

        // 1. prefetch input tile for t+1 into registers (one-pass poll; the
        //    LDG latency is hidden under the full matvec below)
        float4 sv0, sv1;
        float  xv0 = 0.f, xv1 = 0.f;
        const bool pf = (t + 1 < TT);
        if (pf) {
            if (l > 0) {
                while (ldacq(inflag) < t + 2) __nanosleep(128);
                sv0 = *(const float4*)(hxin + ((t + 1) * Hs + k0) * BATCH + bbase + q0 * 4);
                if (v1)
                    sv1 = *(const float4*)(hxin + ((t + 1) * Hs + k1) * BATCH + bbase + q1 * 4);
            } else {
                if (xv0ok) xv0 = xin[(bbase + xb0) * TT * IN0 + (t + 1) * IN0 + xk0];
                if (xv1ok) xv1 = xin[(bbase + xb1) * TT * IN0 + (t + 1) * IN0 + xk1];
            }
        }

        // 2. full matvec: recurrent part (vv) then input part (xs), no barrier
        ull a0[4], a1[4], a2[4], a3[4];
#pragma unroll
        for (int p = 0; p < 4; p++) { a0[p] = b2[0]; a1[p] = b2[1]; a2[p] = b2[2]; a3[p] = b2[3]; }

#pragma unroll 7
        for (int k = 0; k < Hs; k++)
            mstep(ws + (k * Hs + uc) * 8, vvc + k * VP + bh, a0, a1, a2, a3);
#pragma unroll 7
        for (int k = 0; k < kxt; k++)
            mstep(ws + ((Hs + k) * Hs + uc) * 8, xsc + k * VP + bh, a0, a1, a2, a3);

        // 3. cell update + stores
        if (act) {
            float hv[8];
#pragma unroll
            for (int p = 0; p < 4; p++) {
                float i0, i1, f0, f1, g0, g1, o0, o1;
                unpack2(a0[p], i0, i1);
                unpack2(a1[p], f0, f1);
                unpack2(a2[p], g0, g1);
                unpack2(a3[p], o0, o1);
                i0 = sigf(i0); f0 = sigf(f0); g0 = tanha(g0); o0 = sigf(o0);
                i1 = sigf(i1); f1 = sigf(f1); g1 = tanha(g1); o1 = sigf(o1);
                c[2 * p]     = f0 * c[2 * p]     + i0 * g0;
                c[2 * p + 1] = f1 * c[2 * p + 1] + i1 * g1;
                hv[2 * p]     = o0 * tanha(c[2 * p]);
                hv[2 * p + 1] = o1 * tanha(c[2 * p + 1]);
            }
            float* op = hxout + (t * Hs + u) * BATCH + bbase + bh;
            *(float4*)(op)     = make_float4(hv[0], hv[1], hv[2], hv[3]);
            *(float4*)(op + 4) = make_float4(hv[4], hv[5], hv[6], hv[7]);
            *(float4*)(vvn + u * VP + bh)     = make_float4(hv[0], hv[1], hv[2], hv[3]);
            *(float4*)(vvn + u * VP + bh + 4) = make_float4(hv[4], hv[5], hv[6], hv[7]);
        }

        // 4. commit prefetched tile into xs[nxt]
        if (pf) {
            if (l > 0) {
                *(float4*)(xsn + k0 * VP + q0 * 4) = sv0;
                if (v1) *(float4*)(xsn + k1 * VP + q1 * 4) = sv1;
            } else {
                if (xv0ok) xsn[xk0 * VP + xb0] = xv0;
                if (xv1ok) xsn[xk1 * VP + xb1] = xv1;
            }
        }
        __syncthreads();                     // single barrier per step

        // 5. publish step t (h(t) stores drained by the barrier)
        if (tid == 0) strel(outflag, t + 1);
    }
}

// ---------------- final FC ---------------------------------------------------
#define FCB 128
__global__ void fc_kernel(const float* __restrict__ fc_w,
                          const float* __restrict__ fc_b,
                          float* __restrict__ outp) {
    __shared__ float sw[NOUT * Hs];
    __shared__ float sb[NOUT];
    const int t   = blockIdx.x;
    const int bc  = blockIdx.y;
    const int tid = threadIdx.x;

    for (int i = tid; i < NOUT * Hs; i += FCB) sw[i] = fc_w[i];
    if (tid < NOUT) sb[tid] = fc_b[tid];
    __syncthreads();

    const int b = bc * FCB + tid;
    const float* hrow = &g_hx[NL - 1][t][0][0];
    float o[NOUT];
#pragma unroll
    for (int j = 0; j < NOUT; j++) o[j] = sb[j];
#pragma unroll 7
    for (int u = 0; u < Hs; u++) {
        float h = hrow[u * BATCH + b];
#pragma unroll
        for (int j = 0; j < NOUT; j++) o[j] += h * sw[j * Hs + u];
    }
#pragma unroll
    for (int j = 0; j < NOUT; j++)
        outp[(b * TT + t) * NOUT + j] = o[j];
}

// ---------------- launcher ---------------------------------------------------
extern "C" void kernel_launch(void* const* d_in, const int* in_sizes, int n_in,
                              void* d_out, int out_size) {
    const float* x     = (const float*)d_in[0];
    const float* W_ih0 = (const float*)d_in[1];
    const float* W_ihr = (const float*)d_in[2];
    const float* W_hh  = (const float*)d_in[3];
    const float* b_ih  = (const float*)d_in[4];
    const float* b_hh  = (const float*)d_in[5];
    const float* fc_w  = (const float*)d_in[6];
    const float* fc_b  = (const float*)d_in[7];
    float* outp = (float*)d_out;

    cudaFuncSetAttribute(lstm_pipe, cudaFuncAttributeMaxDynamicSharedMemorySize, SMEMB);

    const int total = NL * KT * Hs;
    pack_kernel<<<(total + 255) / 256, 256>>>(W_ih0, W_ihr, W_hh, b_ih, b_hh);
    reset_kernel<<<(NL * GB * 32 + 127) / 128, 128>>>();

    lstm_pipe<<<NL * GB, TPB, SMEMB>>>(x);

    dim3 fcg(TT, BATCH / FCB);
    fc_kernel<<<fcg, FCB>>>(fc_w, fc_b, outp);
}

// round 13
// speedup vs baseline: 3.2655x; 1.8073x over previous
#include <cuda_runtime.h>
#include <cuda_bf16.h>

typedef unsigned int u32;
typedef unsigned short u16;

#define Hs     49
#define G4     196
#define NL     7
#define IN0    7
#define NOUT   7
#define BATCH  1024
#define TT     512

#define GB     16           // slices per layer -> 112 blocks
#define BB     64           // batch rows per block = MMA M
#define TPB    256          // 8 warps, warp = 4 n8-tiles
#define NBP    256          // padded N (32 n8-tiles; units 0..48 real)
#define KK     224          // packed K: [hi 112 | lo 112]
#define HXW    52           // u32 words per (t,b) row of g_hx

#define AROW   528          // A row stride bytes (264 bf16; 528%128=16 -> conflict-free)
#define ABUF   (BB*AROW)    // 33792
#define SMEMB  (2*ABUF)     // 67584

// K map (both hi/lo regions): 0..48 h | 49..97 x | 98 bias-one | 99..111 pad
// B rows n = unit*4 + gate(i,f,g,o); B cols: k<112 -> W_hi (bias_hi at 98),
// k>=112 -> W_lo (bias_lo at 210). Terms: Whi*vhi, Whi*vlo, Wlo*vhi.

// ---------------- device scratch ------------------------------------------
__device__ __nv_bfloat16 g_wpack[NL][NBP][KK];
__device__ u32 g_hx[NL][TT][BATCH][HXW];   // h words: lo16 = hi-part, hi16 = lo-part
__device__ int g_flag[NL][GB][32];

// ---------------- helpers ---------------------------------------------------
static __device__ __forceinline__ u32 smem_u32(const void* p) {
    u32 a; asm("{ .reg .u64 t; cvta.to.shared.u64 t, %1; cvt.u32.u64 %0, t; }"
               : "=r"(a) : "l"(p)); return a;
}
static __device__ __forceinline__ float tanha(float x) {
    float r; asm("tanh.approx.f32 %0, %1;" : "=f"(r) : "f"(x)); return r;
}
static __device__ __forceinline__ float sigf(float x) {
    return fmaf(0.5f, tanha(0.5f * x), 0.5f);
}
static __device__ __forceinline__ int ldacq(const int* p) {
    int v; asm volatile("ld.global.acquire.gpu.b32 %0, [%1];" : "=r"(v) : "l"(p)); return v;
}
static __device__ __forceinline__ void strel(int* p, int v) {
    asm volatile("st.global.release.gpu.b32 [%0], %1;" :: "l"(p), "r"(v));
}

#define LDSM4(r, addr) asm volatile( \
    "ldmatrix.sync.aligned.m8n8.x4.shared.b16 {%0,%1,%2,%3}, [%4];" \
    : "=r"((r)[0]), "=r"((r)[1]), "=r"((r)[2]), "=r"((r)[3]) : "r"(addr))

#define MMA(d, a, b) asm volatile( \
    "mma.sync.aligned.m16n8k16.row.col.f32.bf16.bf16.f32 " \
    "{%0,%1,%2,%3}, {%4,%5,%6,%7}, {%8,%9}, {%0,%1,%2,%3};" \
    : "+f"((d)[0]), "+f"((d)[1]), "+f"((d)[2]), "+f"((d)[3]) \
    : "r"((a)[0]), "r"((a)[1]), "r"((a)[2]), "r"((a)[3]), "r"((b)[0]), "r"((b)[1]))

// ---------------- packing ---------------------------------------------------
__global__ void pack_kernel(const float* __restrict__ W_ih0,
                            const float* __restrict__ W_ihr,
                            const float* __restrict__ W_hh,
                            const float* __restrict__ b_ih,
                            const float* __restrict__ b_hh) {
    int idx = blockIdx.x * blockDim.x + threadIdx.x;
    const int total = NL * NBP * KK;
    if (idx >= total) return;
    int l = idx / (NBP * KK);
    int rem = idx % (NBP * KK);
    int n = rem / KK, k = rem % KK;
    int u = n >> 2, j = n & 3;

    float w = 0.f;
    bool lo = (k >= 112);
    if (u < Hs) {
        int row = j * Hs + u;                       // torch gate order i,f,g,o
        int kk = lo ? k - 112 : k;
        if (kk <= 48) w = W_hh[(l * G4 + row) * Hs + kk];
        else if (kk <= 97) {
            int q = kk - 49;
            w = (l == 0) ? (q < IN0 ? W_ih0[row * IN0 + q] : 0.f)
                         : W_ihr[((l - 1) * G4 + row) * Hs + q];
        } else if (kk == 98) w = b_ih[l * G4 + row] + b_hh[l * G4 + row];
    }
    __nv_bfloat16 hi = __float2bfloat16_rn(w);
    g_wpack[l][n][k] = lo ? __float2bfloat16_rn(w - __bfloat162float(hi)) : hi;
}

__global__ void reset_kernel() {
    int i = blockIdx.x * blockDim.x + threadIdx.x;
    if (i < NL * GB * 32) ((int*)g_flag)[i] = 0;
}

// ---------------- warp-MMA pipelined LSTM -----------------------------------
__global__ __launch_bounds__(TPB, 1)
void lstm_mma(const float* __restrict__ xin) {
    extern __shared__ char sm[];
    const u32 Abase = smem_u32(sm);

    const int bid = blockIdx.x, l = bid / GB, g = bid % GB, bbase = g * BB;
    const int tid = threadIdx.x, ns = tid >> 5, lane = tid & 31;

    // zero both A buffers
    for (int i = tid; i < SMEMB / 4; i += TPB) ((u32*)sm)[i] = 0;

    // ---- load persistent B fragments from gmem (reused 512 steps) ----
    u32 Bh[4][7][2], Bl[4][7][2];
#pragma unroll
    for (int nt = 0; nt < 4; nt++) {
        int n = (ns * 4 + nt) * 8 + (lane >> 2);
        const __nv_bfloat16* wr = &g_wpack[l][n][0];
        int kb0 = (lane & 3) * 2;
#pragma unroll
        for (int kt = 0; kt < 7; kt++) {
            Bh[nt][kt][0] = *(const u32*)(wr + kt * 16 + kb0);
            Bh[nt][kt][1] = *(const u32*)(wr + kt * 16 + kb0 + 8);
            Bl[nt][kt][0] = *(const u32*)(wr + 112 + kt * 16 + kb0);
            Bl[nt][kt][1] = *(const u32*)(wr + 112 + kt * 16 + kb0 + 8);
        }
    }
    __syncthreads();
    // bias-one column (98) in both buffers
    if (tid < BB) {
        *(u16*)(sm + tid * AROW + 98 * 2)        = (u16)0x3F80;
        *(u16*)(sm + ABUF + tid * AROW + 98 * 2) = (u16)0x3F80;
    }

    const int* inflag  = &g_flag[(l == 0 ? 0 : l - 1)][g][0];
    int*       outflag = &g_flag[l][g][0];
    const u32* hxin    = &g_hx[(l == 0 ? 0 : l - 1)][0][0][0];
    u32*       hxout   = &g_hx[l][0][0][0];

    // staging identity: thread -> (row sr, word chunk sj)
    const int sr = tid >> 2, sj = tid & 3;
    const int j0 = sj * 13, jcnt = (j0 < 49) ? ((49 - j0 < 13) ? 49 - j0 : 13) : 0;

    // ---- stage x(0) into buffer 0 ----
    if (l > 0) {
        while (ldacq(inflag) < 1) __nanosleep(128);
        const u32* src = &hxin[(0 * BATCH + bbase + sr) * HXW + j0];
        for (int j = 0; j < jcnt; j++) {
            u32 w = src[j];
            *(u16*)(sm + sr * AROW + (49 + j0 + j) * 2)  = (u16)(w & 0xFFFF);
            *(u16*)(sm + sr * AROW + (161 + j0 + j) * 2) = (u16)(w >> 16);
        }
    } else {
#pragma unroll
        for (int j = 0; j < 2; j++) {
            int jj = sj * 2 + j;
            if (jj < IN0) {
                float f = xin[(bbase + sr) * TT * IN0 + jj];
                __nv_bfloat16 hb = __float2bfloat16_rn(f);
                __nv_bfloat16 lb = __float2bfloat16_rn(f - __bfloat162float(hb));
                *(u16*)(sm + sr * AROW + (49 + jj) * 2)  = __bfloat16_as_ushort(hb);
                *(u16*)(sm + sr * AROW + (161 + jj) * 2) = __bfloat16_as_ushort(lb);
            }
        }
    }
    __syncthreads();

    float cst[4][4];
#pragma unroll
    for (int m = 0; m < 4; m++)
#pragma unroll
        for (int nt = 0; nt < 4; nt++) cst[m][nt] = 0.f;

    const bool evenl = !(lane & 1);
    const int arow15 = lane & 15;
    const int acolo  = (lane & 16) ? 8 : 0;

    for (int t = 0; t < TT; t++) {
        const int cur = t & 1, nxt = cur ^ 1;
        const u32 Acur = Abase + cur * ABUF;
        char* Anx = sm + nxt * ABUF;

        // 1. prefetch x(t+1) into registers (hidden under the MMA)
        u32 wv[13]; float xf[2];
        const bool pf = (t + 1 < TT);
        if (pf) {
            if (l > 0) {
                while (ldacq(inflag) < t + 2) __nanosleep(128);
                const u32* src = &hxin[((t + 1) * BATCH + bbase + sr) * HXW + j0];
                for (int j = 0; j < jcnt; j++) wv[j] = src[j];
            } else {
#pragma unroll
                for (int j = 0; j < 2; j++) {
                    int jj = sj * 2 + j;
                    if (jj < IN0) xf[j] = xin[(bbase + sr) * TT * IN0 + (t + 1) * IN0 + jj];
                }
            }
        }

        // 2. MMA: D[64x256] = A[64x224] x B^T, 3 split-terms
        float acc[4][4][4];
#pragma unroll
        for (int m = 0; m < 4; m++)
#pragma unroll
            for (int nt = 0; nt < 4; nt++)
#pragma unroll
                for (int q = 0; q < 4; q++) acc[m][nt][q] = 0.f;

#pragma unroll
        for (int kt = 0; kt < 14; kt++) {
            u32 a[4][4];
            const u32 cb = (u32)(kt * 16 + acolo) * 2;
#pragma unroll
            for (int m = 0; m < 4; m++) {
                u32 ad = Acur + (u32)(m * 16 + arow15) * AROW + cb;
                LDSM4(a[m], ad);
            }
            if (kt < 7) {
#pragma unroll
                for (int m = 0; m < 4; m++)
#pragma unroll
                    for (int nt = 0; nt < 4; nt++) {
                        MMA(acc[m][nt], a[m], Bh[nt][kt]);   // Whi * vhi
                        MMA(acc[m][nt], a[m], Bl[nt][kt]);   // Wlo * vhi
                    }
            } else {
#pragma unroll
                for (int m = 0; m < 4; m++)
#pragma unroll
                    for (int nt = 0; nt < 4; nt++)
                        MMA(acc[m][nt], a[m], Bh[nt][kt - 7]); // Whi * vlo
            }
        }

        // 3. epilogue: gather 4 gates per cell via one shfl, cell update, store
#pragma unroll
        for (int m = 0; m < 4; m++) {
#pragma unroll
            for (int nt = 0; nt < 4; nt++) {
                float sA = evenl ? acc[m][nt][2] : acc[m][nt][0];
                float sB = evenl ? acc[m][nt][3] : acc[m][nt][1];
                float rA = __shfl_xor_sync(0xFFFFFFFFu, sA, 1);
                float rB = __shfl_xor_sync(0xFFFFFFFFu, sB, 1);
                float i_, f_, g_, o_; int row;
                if (evenl) {
                    i_ = acc[m][nt][0]; f_ = acc[m][nt][1]; g_ = rA; o_ = rB;
                    row = m * 16 + (lane >> 2);
                } else {
                    i_ = rA; f_ = rB; g_ = acc[m][nt][2]; o_ = acc[m][nt][3];
                    row = m * 16 + 8 + (lane >> 2);
                }
                int unit = (ns * 4 + nt) * 2 + ((lane >> 1) & 1);
                float iv = sigf(i_), fv = sigf(f_), gv = tanha(g_), ov = sigf(o_);
                float cc = fv * cst[m][nt] + iv * gv;
                cst[m][nt] = cc;
                float h = ov * tanha(cc);
                if (unit < Hs) {
                    __nv_bfloat16 hb = __float2bfloat16_rn(h);
                    __nv_bfloat16 lb = __float2bfloat16_rn(h - __bfloat162float(hb));
                    u16 hbb = __bfloat16_as_ushort(hb), lbb = __bfloat16_as_ushort(lb);
                    *(u16*)(Anx + row * AROW + unit * 2)         = hbb;
                    *(u16*)(Anx + row * AROW + (112 + unit) * 2) = lbb;
                    hxout[(t * BATCH + bbase + row) * HXW + unit] = (u32)hbb | ((u32)lbb << 16);
                }
            }
        }

        // 4. commit x(t+1) into next buffer
        if (pf) {
            if (l > 0) {
                for (int j = 0; j < jcnt; j++) {
                    *(u16*)(Anx + sr * AROW + (49 + j0 + j) * 2)  = (u16)(wv[j] & 0xFFFF);
                    *(u16*)(Anx + sr * AROW + (161 + j0 + j) * 2) = (u16)(wv[j] >> 16);
                }
            } else {
#pragma unroll
                for (int j = 0; j < 2; j++) {
                    int jj = sj * 2 + j;
                    if (jj < IN0) {
                        __nv_bfloat16 hb = __float2bfloat16_rn(xf[j]);
                        __nv_bfloat16 lb = __float2bfloat16_rn(xf[j] - __bfloat162float(hb));
                        *(u16*)(Anx + sr * AROW + (49 + jj) * 2)  = __bfloat16_as_ushort(hb);
                        *(u16*)(Anx + sr * AROW + (161 + jj) * 2) = __bfloat16_as_ushort(lb);
                    }
                }
            }
        }

        __syncthreads();                         // single barrier per step
        if (tid == 0) strel(outflag, t + 1);     // publish h(t)
    }
}

// ---------------- final FC ---------------------------------------------------
#define FCB 128
__global__ void fc_kernel(const float* __restrict__ fc_w,
                          const float* __restrict__ fc_b,
                          float* __restrict__ outp) {
    __shared__ float sw[NOUT * Hs];
    __shared__ float sb[NOUT];
    const int t = blockIdx.x, bc = blockIdx.y, tid = threadIdx.x;

    for (int i = tid; i < NOUT * Hs; i += FCB) sw[i] = fc_w[i];
    if (tid < NOUT) sb[tid] = fc_b[tid];
    __syncthreads();

    const int b = bc * FCB + tid;
    const u32* hrow = &g_hx[NL - 1][t][b][0];
    float o[NOUT];
#pragma unroll
    for (int j = 0; j < NOUT; j++) o[j] = sb[j];
#pragma unroll 7
    for (int u = 0; u < Hs; u++) {
        u32 w = hrow[u];
        __nv_bfloat16_raw rh; rh.x = (u16)(w & 0xFFFF);
        __nv_bfloat16_raw rl; rl.x = (u16)(w >> 16);
        float h = __bfloat162float(__nv_bfloat16(rh)) + __bfloat162float(__nv_bfloat16(rl));
#pragma unroll
        for (int j = 0; j < NOUT; j++) o[j] += h * sw[j * Hs + u];
    }
#pragma unroll
    for (int j = 0; j < NOUT; j++)
        outp[(b * TT + t) * NOUT + j] = o[j];
}

// ---------------- launcher ---------------------------------------------------
extern "C" void kernel_launch(void* const* d_in, const int* in_sizes, int n_in,
                              void* d_out, int out_size) {
    const float* x     = (const float*)d_in[0];
    const float* W_ih0 = (const float*)d_in[1];
    const float* W_ihr = (const float*)d_in[2];
    const float* W_hh  = (const float*)d_in[3];
    const float* b_ih  = (const float*)d_in[4];
    const float* b_hh  = (const float*)d_in[5];
    const float* fc_w  = (const float*)d_in[6];
    const float* fc_b  = (const float*)d_in[7];
    float* outp = (float*)d_out;

    cudaFuncSetAttribute(lstm_mma, cudaFuncAttributeMaxDynamicSharedMemorySize, SMEMB);

    const int total = NL * NBP * KK;
    pack_kernel<<<(total + 255) / 256, 256>>>(W_ih0, W_ihr, W_hh, b_ih, b_hh);
    reset_kernel<<<(NL * GB * 32 + 127) / 128, 128>>>();

    lstm_mma<<<NL * GB, TPB, SMEMB>>>(x);

    dim3 fcg(TT, BATCH / FCB);
    fc_kernel<<<fcg, FCB>>>(fc_w, fc_b, outp);
}

// round 14
// speedup vs baseline: 3.6330x; 1.1125x over previous
#include <cuda_runtime.h>
#include <cuda_fp16.h>

typedef unsigned long long ull;
typedef unsigned int u32;
typedef unsigned short u16;

#define Hs     49
#define G4     196
#define NL     7
#define IN0    7
#define NOUT   7
#define BATCH  1024
#define TT     512

#define GB     16           // slices per layer -> 112 blocks
#define BB     64           // batch rows per block = MMA M
#define TPB    320          // 10 warps
#define NBP    208          // 26 n8-tiles (units 0..48 real, 52 slots)
#define KB     112          // B K-extent (7 k16-tiles)
#define HXW    52           // u32 words per (t,b) row of g_hx

#define AROW   528          // A row stride bytes (conflict-free: 528 % 128 = 16)
#define ABUF   (BB*AROW)
#define SMEMB  (2*ABUF)     // 67584

// A cols: vhi[ h 0..48 | x 49..97 | bias1 98 | pad ] , vlo same +112 (bias-lo=0)
// B rows n = unit*4 + gate(i,f,g,o), K = 112 (single fp16 W, bias at k=98)
// Terms: Whi*vhi (kt 0..6) + Whi*vlo (kt 7..13, same B frags)

// warp->tile map: tiles {3,3,3,3,2,2,3,3,2,2}, bases {0,3,6,9,12,14,16,19,22,24}
// per-SMSP tiles: {7,7,6,6}
#define TBPK (0ULL|(3ULL<<6)|(6ULL<<12)|(9ULL<<18)|(12ULL<<24)|(14ULL<<30)|(16ULL<<36)|(19ULL<<42)|(22ULL<<48)|(24ULL<<54))
#define NTPK (3u|(3u<<3)|(3u<<6)|(3u<<9)|(2u<<12)|(2u<<15)|(3u<<18)|(3u<<21)|(2u<<24)|(2u<<27))

// ---------------- device scratch ------------------------------------------
__device__ __half g_wpack[NL][NBP][KB];
__device__ u32 g_hx[NL][TT][BATCH][HXW];   // h words: lo16 = hi-part, hi16 = lo-part (fp16)
__device__ int g_flag[NL][GB][32];

// ---------------- helpers ---------------------------------------------------
static __device__ __forceinline__ u32 smem_u32(const void* p) {
    u32 a; asm("{ .reg .u64 t; cvta.to.shared.u64 t, %1; cvt.u32.u64 %0, t; }"
               : "=r"(a) : "l"(p)); return a;
}
static __device__ __forceinline__ float tanha(float x) {
    float r; asm("tanh.approx.f32 %0, %1;" : "=f"(r) : "f"(x)); return r;
}
static __device__ __forceinline__ float sigf(float x) {
    return fmaf(0.5f, tanha(0.5f * x), 0.5f);
}
static __device__ __forceinline__ int ldacq(const int* p) {
    int v; asm volatile("ld.global.acquire.gpu.b32 %0, [%1];" : "=r"(v) : "l"(p)); return v;
}
static __device__ __forceinline__ void strel(int* p, int v) {
    asm volatile("st.global.release.gpu.b32 [%0], %1;" :: "l"(p), "r"(v));
}
static __device__ __forceinline__ u32 h2pack(float v) {   // (hi | lo<<16) fp16 split
    __half hb = __float2half_rn(v);
    __half lb = __float2half_rn(v - __half2float(hb));
    return (u32)__half_as_ushort(hb) | ((u32)__half_as_ushort(lb) << 16);
}

#define LDSM4(r, addr) asm volatile( \
    "ldmatrix.sync.aligned.m8n8.x4.shared.b16 {%0,%1,%2,%3}, [%4];" \
    : "=r"((r)[0]), "=r"((r)[1]), "=r"((r)[2]), "=r"((r)[3]) : "r"(addr))

#define MMA(d, a, b) asm volatile( \
    "mma.sync.aligned.m16n8k16.row.col.f32.f16.f16.f32 " \
    "{%0,%1,%2,%3}, {%4,%5,%6,%7}, {%8,%9}, {%0,%1,%2,%3};" \
    : "+f"((d)[0]), "+f"((d)[1]), "+f"((d)[2]), "+f"((d)[3]) \
    : "r"((a)[0]), "r"((a)[1]), "r"((a)[2]), "r"((a)[3]), "r"((b)[0]), "r"((b)[1]))

// ---------------- packing ---------------------------------------------------
__global__ void pack_kernel(const float* __restrict__ W_ih0,
                            const float* __restrict__ W_ihr,
                            const float* __restrict__ W_hh,
                            const float* __restrict__ b_ih,
                            const float* __restrict__ b_hh) {
    int idx = blockIdx.x * blockDim.x + threadIdx.x;
    const int total = NL * NBP * KB;
    if (idx >= total) return;
    int l = idx / (NBP * KB);
    int rem = idx % (NBP * KB);
    int n = rem / KB, k = rem % KB;
    int u = n >> 2, j = n & 3;

    float w = 0.f;
    if (u < Hs) {
        int row = j * Hs + u;                       // torch gate order i,f,g,o
        if (k <= 48) w = W_hh[(l * G4 + row) * Hs + k];
        else if (k <= 97) {
            int q = k - 49;
            w = (l == 0) ? (q < IN0 ? W_ih0[row * IN0 + q] : 0.f)
                         : W_ihr[((l - 1) * G4 + row) * Hs + q];
        } else if (k == 98) w = b_ih[l * G4 + row] + b_hh[l * G4 + row];
    }
    g_wpack[l][n][k] = __float2half_rn(w);
}

__global__ void reset_kernel() {
    int i = blockIdx.x * blockDim.x + threadIdx.x;
    if (i < NL * GB * 32) ((int*)g_flag)[i] = 0;
}

// ---------------- warp-MMA pipelined LSTM -----------------------------------
__global__ __launch_bounds__(TPB, 1)
void lstm_mma(const float* __restrict__ xin) {
    extern __shared__ char sm[];
    const u32 Abase = smem_u32(sm);

    const int bid = blockIdx.x, l = bid / GB, g = bid % GB, bbase = g * BB;
    const int tid = threadIdx.x, ws = tid >> 5, lane = tid & 31;
    const int tb  = (int)((TBPK >> (ws * 6)) & 63);
    const int ntc = (int)((NTPK >> (ws * 3)) & 7);

    // zero both A buffers
    for (int i = tid; i < SMEMB / 4; i += TPB) ((u32*)sm)[i] = 0;

    // ---- persistent B fragments (fp16 W, reused 512 steps) ----
    u32 Bh[3][7][2];
#pragma unroll
    for (int nt = 0; nt < 3; nt++) {
        if (nt < ntc) {
            int n = (tb + nt) * 8 + (lane >> 2);
            const __half* wr = &g_wpack[l][n][0];
            int kb0 = (lane & 3) * 2;
#pragma unroll
            for (int kt = 0; kt < 7; kt++) {
                Bh[nt][kt][0] = *(const u32*)(wr + kt * 16 + kb0);
                Bh[nt][kt][1] = *(const u32*)(wr + kt * 16 + kb0 + 8);
            }
        }
    }
    __syncthreads();
    // bias-one column (98, hi region) in both buffers
    if (tid < BB) {
        *(u16*)(sm + tid * AROW + 98 * 2)        = (u16)0x3C00;
        *(u16*)(sm + ABUF + tid * AROW + 98 * 2) = (u16)0x3C00;
    }

    const int* inflag  = &g_flag[(l == 0 ? 0 : l - 1)][g][0];
    int*       outflag = &g_flag[l][g][0];
    const u32* hxin    = &g_hx[(l == 0 ? 0 : l - 1)][0][0][0];
    u32*       hxout   = &g_hx[l][0][0][0];

    // staging identity: 5 threads per batch row, 10 words each
    const int sr = tid / 5, sj = tid % 5;
    const int j0 = sj * 10, jcnt = (49 - j0 < 10) ? 49 - j0 : 10;

    // ---- stage x(0) into buffer 0 ----
    if (l > 0) {
        while (ldacq(inflag) < 1) __nanosleep(128);
        const u32* src = &hxin[(0 * BATCH + bbase + sr) * HXW + j0];
        for (int j = 0; j < jcnt; j++) {
            u32 w = src[j];
            *(u16*)(sm + sr * AROW + (49 + j0 + j) * 2)  = (u16)(w & 0xFFFF);
            *(u16*)(sm + sr * AROW + (161 + j0 + j) * 2) = (u16)(w >> 16);
        }
    } else {
#pragma unroll
        for (int j = 0; j < 2; j++) {
            int jj = sj * 2 + j;
            if (jj < IN0) {
                u32 w = h2pack(xin[(bbase + sr) * TT * IN0 + jj]);
                *(u16*)(sm + sr * AROW + (49 + jj) * 2)  = (u16)(w & 0xFFFF);
                *(u16*)(sm + sr * AROW + (161 + jj) * 2) = (u16)(w >> 16);
            }
        }
    }
    __syncthreads();

    float cst[3][4];
#pragma unroll
    for (int nt = 0; nt < 3; nt++)
#pragma unroll
        for (int m = 0; m < 4; m++) cst[nt][m] = 0.f;

    const bool evenl = !(lane & 1);
    const int arow15 = lane & 15;
    const int acolo  = (lane & 16) ? 8 : 0;

    for (int t = 0; t < TT; t++) {
        const int cur = t & 1, nxt = cur ^ 1;
        const u32 Acur = Abase + cur * ABUF;
        char* Anx = sm + nxt * ABUF;

        // 1. prefetch x(t+1) into registers (hidden under the MMA)
        u32 wv[10]; float xf[2];
        const bool pf = (t + 1 < TT);
        if (pf) {
            if (l > 0) {
                while (ldacq(inflag) < t + 2) __nanosleep(128);
                const u32* src = &hxin[((t + 1) * BATCH + bbase + sr) * HXW + j0];
                for (int j = 0; j < jcnt; j++) wv[j] = src[j];
            } else {
#pragma unroll
                for (int j = 0; j < 2; j++) {
                    int jj = sj * 2 + j;
                    if (jj < IN0) xf[j] = xin[(bbase + sr) * TT * IN0 + (t + 1) * IN0 + jj];
                }
            }
        }

        // 2. MMA: D[64x208] = A[64x224] x B^T, 2 fp16 terms (vhi, vlo with same W)
        float acc[3][4][4];
#pragma unroll
        for (int nt = 0; nt < 3; nt++)
#pragma unroll
            for (int m = 0; m < 4; m++)
#pragma unroll
                for (int q = 0; q < 4; q++) acc[nt][m][q] = 0.f;

#pragma unroll
        for (int kt = 0; kt < 14; kt++) {
            const int kb = (kt < 7) ? kt : kt - 7;
            u32 a[4][4];
            const u32 cb = (u32)(kt * 16 + acolo) * 2;
#pragma unroll
            for (int m = 0; m < 4; m++) {
                u32 ad = Acur + (u32)(m * 16 + arow15) * AROW + cb;
                LDSM4(a[m], ad);
            }
#pragma unroll
            for (int m = 0; m < 4; m++)
#pragma unroll
                for (int nt = 0; nt < 3; nt++)
                    if (nt < ntc) MMA(acc[nt][m], a[m], Bh[nt][kb]);
        }

        // 3. epilogue: gather 4 gates per cell via one shfl, cell update, store
#pragma unroll
        for (int nt = 0; nt < 3; nt++) {
            if (nt < ntc) {
#pragma unroll
                for (int m = 0; m < 4; m++) {
                    float sA = evenl ? acc[nt][m][2] : acc[nt][m][0];
                    float sB = evenl ? acc[nt][m][3] : acc[nt][m][1];
                    float rA = __shfl_xor_sync(0xFFFFFFFFu, sA, 1);
                    float rB = __shfl_xor_sync(0xFFFFFFFFu, sB, 1);
                    float i_, f_, g_, o_; int row;
                    if (evenl) {
                        i_ = acc[nt][m][0]; f_ = acc[nt][m][1]; g_ = rA; o_ = rB;
                        row = m * 16 + (lane >> 2);
                    } else {
                        i_ = rA; f_ = rB; g_ = acc[nt][m][2]; o_ = acc[nt][m][3];
                        row = m * 16 + 8 + (lane >> 2);
                    }
                    int unit = (tb + nt) * 2 + ((lane >> 1) & 1);
                    float iv = sigf(i_), fv = sigf(f_), gv = tanha(g_), ov = sigf(o_);
                    float cc = fv * cst[nt][m] + iv * gv;
                    cst[nt][m] = cc;
                    float h = ov * tanha(cc);
                    if (unit < Hs) {
                        u32 w = h2pack(h);
                        *(u16*)(Anx + row * AROW + unit * 2)         = (u16)(w & 0xFFFF);
                        *(u16*)(Anx + row * AROW + (112 + unit) * 2) = (u16)(w >> 16);
                        hxout[(t * BATCH + bbase + row) * HXW + unit] = w;
                    }
                }
            }
        }

        // 4. commit x(t+1) into next buffer
        if (pf) {
            if (l > 0) {
                for (int j = 0; j < jcnt; j++) {
                    *(u16*)(Anx + sr * AROW + (49 + j0 + j) * 2)  = (u16)(wv[j] & 0xFFFF);
                    *(u16*)(Anx + sr * AROW + (161 + j0 + j) * 2) = (u16)(wv[j] >> 16);
                }
            } else {
#pragma unroll
                for (int j = 0; j < 2; j++) {
                    int jj = sj * 2 + j;
                    if (jj < IN0) {
                        u32 w = h2pack(xf[j]);
                        *(u16*)(Anx + sr * AROW + (49 + jj) * 2)  = (u16)(w & 0xFFFF);
                        *(u16*)(Anx + sr * AROW + (161 + jj) * 2) = (u16)(w >> 16);
                    }
                }
            }
        }

        __syncthreads();                         // single barrier per step
        if (tid == 0) strel(outflag, t + 1);     // publish h(t)
    }
}

// ---------------- final FC ---------------------------------------------------
#define FCB 128
__global__ void fc_kernel(const float* __restrict__ fc_w,
                          const float* __restrict__ fc_b,
                          float* __restrict__ outp) {
    __shared__ float sw[NOUT * Hs];
    __shared__ float sb[NOUT];
    const int t = blockIdx.x, bc = blockIdx.y, tid = threadIdx.x;

    for (int i = tid; i < NOUT * Hs; i += FCB) sw[i] = fc_w[i];
    if (tid < NOUT) sb[tid] = fc_b[tid];
    __syncthreads();

    const int b = bc * FCB + tid;
    const u32* hrow = &g_hx[NL - 1][t][b][0];
    float o[NOUT];
#pragma unroll
    for (int j = 0; j < NOUT; j++) o[j] = sb[j];
#pragma unroll 7
    for (int u = 0; u < Hs; u++) {
        u32 w = hrow[u];
        __half_raw rh; rh.x = (u16)(w & 0xFFFF);
        __half_raw rl; rl.x = (u16)(w >> 16);
        float h = __half2float(__half(rh)) + __half2float(__half(rl));
#pragma unroll
        for (int j = 0; j < NOUT; j++) o[j] += h * sw[j * Hs + u];
    }
#pragma unroll
    for (int j = 0; j < NOUT; j++)
        outp[(b * TT + t) * NOUT + j] = o[j];
}

// ---------------- launcher ---------------------------------------------------
extern "C" void kernel_launch(void* const* d_in, const int* in_sizes, int n_in,
                              void* d_out, int out_size) {
    const float* x     = (const float*)d_in[0];
    const float* W_ih0 = (const float*)d_in[1];
    const float* W_ihr = (const float*)d_in[2];
    const float* W_hh  = (const float*)d_in[3];
    const float* b_ih  = (const float*)d_in[4];
    const float* b_hh  = (const float*)d_in[5];
    const float* fc_w  = (const float*)d_in[6];
    const float* fc_b  = (const float*)d_in[7];
    float* outp = (float*)d_out;

    cudaFuncSetAttribute(lstm_mma, cudaFuncAttributeMaxDynamicSharedMemorySize, SMEMB);

    const int total = NL * NBP * KB;
    pack_kernel<<<(total + 255) / 256, 256>>>(W_ih0, W_ihr, W_hh, b_ih, b_hh);
    reset_kernel<<<(NL * GB * 32 + 127) / 128, 128>>>();

    lstm_mma<<<NL * GB, TPB, SMEMB>>>(x);

    dim3 fcg(TT, BATCH / FCB);
    fc_kernel<<<fcg, FCB>>>(fc_w, fc_b, outp);
}

// round 15
// speedup vs baseline: 6.2713x; 1.7262x over previous
#include <cuda_runtime.h>
#include <cuda_fp16.h>

typedef unsigned int u32;
typedef unsigned short u16;

#define Hs     49
#define G4     196
#define NL     7
#define IN0    7
#define NOUT   7
#define BATCH  1024
#define TT     512

#define GB     16           // slices per layer -> 112 blocks
#define BB     64           // batch rows per block = MMA M
#define TPB    320          // 10 warps
#define NBP    208          // 26 n8-tiles (units 0..48 real)
#define KB     112          // K extent: h 0..48 | bias 49 | x 50..98 | pad ..111
#define HXU    56           // u16 units per (t,b) row of g_hx (49 real + pad)

#define AROW   240          // A row stride bytes (15*16B, odd multiple -> LDSM conflict-free)
#define ABUF   (BB*AROW)    // 15360
#define SMEMB  (2*ABUF)     // 30720

// warp->n-tile map: tiles {3,3,3,3,2,2,3,3,2,2}, bases {0,3,6,9,12,14,16,19,22,24}
#define TBPK (0ULL|(3ULL<<6)|(6ULL<<12)|(9ULL<<18)|(12ULL<<24)|(14ULL<<30)|(16ULL<<36)|(19ULL<<42)|(22ULL<<48)|(24ULL<<54))
#define NTPK (3u|(3u<<3)|(3u<<6)|(3u<<9)|(2u<<12)|(2u<<15)|(3u<<18)|(3u<<21)|(2u<<24)|(2u<<27))

// ---------------- device scratch ------------------------------------------
__device__ __half g_wpack[NL][NBP][KB];
__device__ u16 g_hx[NL][TT][BATCH][HXU];   // h as single fp16
__device__ int g_flag[NL][GB][32];

// ---------------- helpers ---------------------------------------------------
static __device__ __forceinline__ u32 smem_u32(const void* p) {
    u32 a; asm("{ .reg .u64 t; cvta.to.shared.u64 t, %1; cvt.u32.u64 %0, t; }"
               : "=r"(a) : "l"(p)); return a;
}
static __device__ __forceinline__ float tanha(float x) {
    float r; asm("tanh.approx.f32 %0, %1;" : "=f"(r) : "f"(x)); return r;
}
static __device__ __forceinline__ float sigf(float x) {
    return fmaf(0.5f, tanha(0.5f * x), 0.5f);
}
static __device__ __forceinline__ int ldacq(const int* p) {
    int v; asm volatile("ld.global.acquire.gpu.b32 %0, [%1];" : "=r"(v) : "l"(p)); return v;
}
static __device__ __forceinline__ void strel(int* p, int v) {
    asm volatile("st.global.release.gpu.b32 [%0], %1;" :: "l"(p), "r"(v));
}

#define LDSM4(r, addr) asm volatile( \
    "ldmatrix.sync.aligned.m8n8.x4.shared.b16 {%0,%1,%2,%3}, [%4];" \
    : "=r"((r)[0]), "=r"((r)[1]), "=r"((r)[2]), "=r"((r)[3]) : "r"(addr))

#define MMA(d, a, b) asm volatile( \
    "mma.sync.aligned.m16n8k16.row.col.f32.f16.f16.f32 " \
    "{%0,%1,%2,%3}, {%4,%5,%6,%7}, {%8,%9}, {%0,%1,%2,%3};" \
    : "+f"((d)[0]), "+f"((d)[1]), "+f"((d)[2]), "+f"((d)[3]) \
    : "r"((a)[0]), "r"((a)[1]), "r"((a)[2]), "r"((a)[3]), "r"((b)[0]), "r"((b)[1]))

// ---------------- packing ---------------------------------------------------
__global__ void pack_kernel(const float* __restrict__ W_ih0,
                            const float* __restrict__ W_ihr,
                            const float* __restrict__ W_hh,
                            const float* __restrict__ b_ih,
                            const float* __restrict__ b_hh) {
    int idx = blockIdx.x * blockDim.x + threadIdx.x;
    const int total = NL * NBP * KB;
    if (idx >= total) return;
    int l = idx / (NBP * KB);
    int rem = idx % (NBP * KB);
    int n = rem / KB, k = rem % KB;
    int u = n >> 2, j = n & 3;

    float w = 0.f;
    if (u < Hs) {
        int row = j * Hs + u;                       // torch gate order i,f,g,o
        if (k <= 48)       w = W_hh[(l * G4 + row) * Hs + k];
        else if (k == 49)  w = b_ih[l * G4 + row] + b_hh[l * G4 + row];
        else if (k <= 98) {
            int q = k - 50;
            w = (l == 0) ? (q < IN0 ? W_ih0[row * IN0 + q] : 0.f)
                         : W_ihr[((l - 1) * G4 + row) * Hs + q];
        }
    }
    g_wpack[l][n][k] = __float2half_rn(w);
}

__global__ void reset_kernel() {
    int i = blockIdx.x * blockDim.x + threadIdx.x;
    if (i < NL * GB * 32) ((int*)g_flag)[i] = 0;
}

// ---------------- warp-MMA pipelined LSTM -----------------------------------
__global__ __launch_bounds__(TPB, 1)
void lstm_mma(const float* __restrict__ xin) {
    extern __shared__ char sm[];
    const u32 Abase = smem_u32(sm);

    const int bid = blockIdx.x, l = bid / GB, g = bid % GB, bbase = g * BB;
    const int tid = threadIdx.x, ws = tid >> 5, lane = tid & 31;
    const int tb  = (int)((TBPK >> (ws * 6)) & 63);
    const int ntc = (int)((NTPK >> (ws * 3)) & 7);

    // zero both A buffers
    for (int i = tid; i < SMEMB / 4; i += TPB) ((u32*)sm)[i] = 0;

    // ---- persistent B fragments (fp16 W, reused 512 steps) ----
    u32 Bh[3][7][2];
#pragma unroll
    for (int nt = 0; nt < 3; nt++) {
        if (nt < ntc) {
            int n = (tb + nt) * 8 + (lane >> 2);
            const __half* wr = &g_wpack[l][n][0];
            int kb0 = (lane & 3) * 2;
#pragma unroll
            for (int kt = 0; kt < 7; kt++) {
                Bh[nt][kt][0] = *(const u32*)(wr + kt * 16 + kb0);
                Bh[nt][kt][1] = *(const u32*)(wr + kt * 16 + kb0 + 8);
            }
        }
    }
    __syncthreads();
    // bias-one column (49) in both buffers
    if (tid < BB) {
        *(u16*)(sm + tid * AROW + 49 * 2)        = (u16)0x3C00;
        *(u16*)(sm + ABUF + tid * AROW + 49 * 2) = (u16)0x3C00;
    }

    const int* inflag  = &g_flag[(l == 0 ? 0 : l - 1)][g][0];
    int*       outflag = &g_flag[l][g][0];
    const u16* hxin    = &g_hx[(l == 0 ? 0 : l - 1)][0][0][0];
    u16*       hxout   = &g_hx[l][0][0][0];

    // staging identity: 4 threads per batch row (tid<256), 7 u32 words each
    const int sr = tid >> 2, sj = tid & 3;
    const int j0 = sj * 7;                  // u32 index within 28-word row
    const bool stg = (tid < 256);

    // ---- stage x(0) into buffer 0 ----
    if (l > 0) {
        while (ldacq(inflag) < 1) __nanosleep(128);
        if (stg) {
            const u32* src = (const u32*)&hxin[(0 * BATCH + bbase + sr) * HXU] + j0;
#pragma unroll
            for (int j = 0; j < 7; j++)
                *(u32*)(sm + sr * AROW + (50 + 2 * (j0 + j)) * 2) = src[j];
        }
    } else if (stg) {
#pragma unroll
        for (int j = 0; j < 2; j++) {
            int jj = sj * 2 + j;
            if (jj < IN0) {
                __half hb = __float2half_rn(xin[(bbase + sr) * TT * IN0 + jj]);
                *(u16*)(sm + sr * AROW + (50 + jj) * 2) = __half_as_ushort(hb);
            }
        }
    }
    __syncthreads();

    float cst[3][4];
#pragma unroll
    for (int nt = 0; nt < 3; nt++)
#pragma unroll
        for (int m = 0; m < 4; m++) cst[nt][m] = 0.f;

    const bool evenl = !(lane & 1);
    const int arow15 = lane & 15;
    const int acolo  = (lane & 16) ? 8 : 0;

    for (int t = 0; t < TT; t++) {
        const int cur = t & 1, nxt = cur ^ 1;
        const u32 Acur = Abase + cur * ABUF;
        char* Anx = sm + nxt * ABUF;

        // 1. prefetch x(t+1) into registers (hidden under the MMA)
        u32 wv[7]; float xf[2];
        const bool pf = (t + 1 < TT);
        if (pf) {
            if (l > 0) {
                while (ldacq(inflag) < t + 2) __nanosleep(128);
                if (stg) {
                    const u32* src = (const u32*)&hxin[((t + 1) * BATCH + bbase + sr) * HXU] + j0;
#pragma unroll
                    for (int j = 0; j < 7; j++) wv[j] = src[j];
                }
            } else if (stg) {
#pragma unroll
                for (int j = 0; j < 2; j++) {
                    int jj = sj * 2 + j;
                    if (jj < IN0) xf[j] = xin[(bbase + sr) * TT * IN0 + (t + 1) * IN0 + jj];
                }
            }
        }

        // 2. MMA: D[64x208] = A[64x112] x B^T   (7 k-tiles, single fp16)
        float acc[3][4][4];
#pragma unroll
        for (int nt = 0; nt < 3; nt++)
#pragma unroll
            for (int m = 0; m < 4; m++)
#pragma unroll
                for (int q = 0; q < 4; q++) acc[nt][m][q] = 0.f;

#pragma unroll
        for (int kt = 0; kt < 7; kt++) {
            u32 a[4][4];
            const u32 cb = (u32)(kt * 16 + acolo) * 2;
#pragma unroll
            for (int m = 0; m < 4; m++) {
                u32 ad = Acur + (u32)(m * 16 + arow15) * AROW + cb;
                LDSM4(a[m], ad);
            }
#pragma unroll
            for (int m = 0; m < 4; m++)
#pragma unroll
                for (int nt = 0; nt < 3; nt++)
                    if (nt < ntc) MMA(acc[nt][m], a[m], Bh[nt][kt]);
        }

        // 3. epilogue: gather 4 gates per cell via one shfl, cell update, store
#pragma unroll
        for (int nt = 0; nt < 3; nt++) {
            if (nt < ntc) {
#pragma unroll
                for (int m = 0; m < 4; m++) {
                    float sA = evenl ? acc[nt][m][2] : acc[nt][m][0];
                    float sB = evenl ? acc[nt][m][3] : acc[nt][m][1];
                    float rA = __shfl_xor_sync(0xFFFFFFFFu, sA, 1);
                    float rB = __shfl_xor_sync(0xFFFFFFFFu, sB, 1);
                    float i_, f_, g_, o_; int row;
                    if (evenl) {
                        i_ = acc[nt][m][0]; f_ = acc[nt][m][1]; g_ = rA; o_ = rB;
                        row = m * 16 + (lane >> 2);
                    } else {
                        i_ = rA; f_ = rB; g_ = acc[nt][m][2]; o_ = acc[nt][m][3];
                        row = m * 16 + 8 + (lane >> 2);
                    }
                    int unit = (tb + nt) * 2 + ((lane >> 1) & 1);
                    float iv = sigf(i_), fv = sigf(f_), gv = tanha(g_), ov = sigf(o_);
                    float cc = fv * cst[nt][m] + iv * gv;
                    cst[nt][m] = cc;
                    float h = ov * tanha(cc);
                    if (unit < Hs) {
                        u16 hb = __half_as_ushort(__float2half_rn(h));
                        *(u16*)(Anx + row * AROW + unit * 2) = hb;
                        hxout[(t * BATCH + bbase + row) * HXU + unit] = hb;
                    }
                }
            }
        }

        // 4. commit x(t+1) into next buffer
        if (pf && stg) {
            if (l > 0) {
#pragma unroll
                for (int j = 0; j < 7; j++)
                    *(u32*)(Anx + sr * AROW + (50 + 2 * (j0 + j)) * 2) = wv[j];
            } else {
#pragma unroll
                for (int j = 0; j < 2; j++) {
                    int jj = sj * 2 + j;
                    if (jj < IN0) {
                        __half hb = __float2half_rn(xf[j]);
                        *(u16*)(Anx + sr * AROW + (50 + jj) * 2) = __half_as_ushort(hb);
                    }
                }
            }
        }

        __syncthreads();                         // single barrier per step
        if (tid == 0) strel(outflag, t + 1);     // publish h(t)
    }
}

// ---------------- final FC ---------------------------------------------------
#define FCB 128
__global__ void fc_kernel(const float* __restrict__ fc_w,
                          const float* __restrict__ fc_b,
                          float* __restrict__ outp) {
    __shared__ float sw[NOUT * Hs];
    __shared__ float sb[NOUT];
    const int t = blockIdx.x, bc = blockIdx.y, tid = threadIdx.x;

    for (int i = tid; i < NOUT * Hs; i += FCB) sw[i] = fc_w[i];
    if (tid < NOUT) sb[tid] = fc_b[tid];
    __syncthreads();

    const int b = bc * FCB + tid;
    const u32* hrow = (const u32*)&g_hx[NL - 1][t][b][0];
    float o[NOUT];
#pragma unroll
    for (int j = 0; j < NOUT; j++) o[j] = sb[j];
#pragma unroll
    for (int p = 0; p < 25; p++) {                 // 25 u32 = units 0..49 (49 masked below)
        u32 w = hrow[p];
        __half_raw r0; r0.x = (u16)(w & 0xFFFF);
        __half_raw r1; r1.x = (u16)(w >> 16);
        float h0 = __half2float(__half(r0));
        float h1 = (2 * p + 1 < Hs) ? __half2float(__half(r1)) : 0.f;
#pragma unroll
        for (int j = 0; j < NOUT; j++) {
            o[j] += h0 * sw[j * Hs + 2 * p];
            if (2 * p + 1 < Hs) o[j] += h1 * sw[j * Hs + 2 * p + 1];
        }
    }
#pragma unroll
    for (int j = 0; j < NOUT; j++)
        outp[(b * TT + t) * NOUT + j] = o[j];
}

// ---------------- launcher ---------------------------------------------------
extern "C" void kernel_launch(void* const* d_in, const int* in_sizes, int n_in,
                              void* d_out, int out_size) {
    const float* x     = (const float*)d_in[0];
    const float* W_ih0 = (const float*)d_in[1];
    const float* W_ihr = (const float*)d_in[2];
    const float* W_hh  = (const float*)d_in[3];
    const float* b_ih  = (const float*)d_in[4];
    const float* b_hh  = (const float*)d_in[5];
    const float* fc_w  = (const float*)d_in[6];
    const float* fc_b  = (const float*)d_in[7];
    float* outp = (float*)d_out;

    cudaFuncSetAttribute(lstm_mma, cudaFuncAttributeMaxDynamicSharedMemorySize, SMEMB);

    const int total = NL * NBP * KB;
    pack_kernel<<<(total + 255) / 256, 256>>>(W_ih0, W_ihr, W_hh, b_ih, b_hh);
    reset_kernel<<<(NL * GB * 32 + 127) / 128, 128>>>();

    lstm_mma<<<NL * GB, TPB, SMEMB>>>(x);

    dim3 fcg(TT, BATCH / FCB);
    fc_kernel<<<fcg, FCB>>>(fc_w, fc_b, outp);
}

// round 16
// speedup vs baseline: 6.5524x; 1.0448x over previous
#include <cuda_runtime.h>
#include <cuda_fp16.h>

typedef unsigned int u32;
typedef unsigned short u16;

#define Hs     49
#define G4     196
#define NL     7
#define IN0    7
#define NOUT   7
#define BATCH  1024
#define TT     512

#define GB     16           // slices per layer -> 112 blocks
#define BB     64           // batch rows per block = MMA M
#define TPB    352          // 8 MMA warps + 3 scalar/staging warps
#define NBP    208          // packed B rows (52 units x 4 gates)
#define KB     112          // K: h 0..48 | bias 49 | x 50..98 | pad ..111
#define HXU    56           // u16 units per (t,b) row of g_hx

#define AROW   240          // A row stride bytes (15*16B -> LDSM conflict-free)
#define ABUF   (BB*AROW)    // 15360
#define SM_W48 (KB*4*4)     // 1792 B fp32 W for unit 48
#define SMEMB  (2*ABUF + SM_W48)

// ---------------- device scratch ------------------------------------------
__device__ __half g_wpack[NL][NBP][KB];
__device__ float  g_w48[NL][KB][4];        // unit-48 W, [k][gate] fp32
__device__ u16 g_hx[NL][TT][BATCH][HXU];   // h as fp16 (pads stay 0)
__device__ int g_flag[NL][GB][32];

// ---------------- helpers ---------------------------------------------------
static __device__ __forceinline__ u32 smem_u32(const void* p) {
    u32 a; asm("{ .reg .u64 t; cvta.to.shared.u64 t, %1; cvt.u32.u64 %0, t; }"
               : "=r"(a) : "l"(p)); return a;
}
static __device__ __forceinline__ float tanha(float x) {
    float r; asm("tanh.approx.f32 %0, %1;" : "=f"(r) : "f"(x)); return r;
}
static __device__ __forceinline__ float sigf(float x) {
    return fmaf(0.5f, tanha(0.5f * x), 0.5f);
}
static __device__ __forceinline__ int ldacq(const int* p) {
    int v; asm volatile("ld.global.acquire.gpu.b32 %0, [%1];" : "=r"(v) : "l"(p)); return v;
}
static __device__ __forceinline__ void strel(int* p, int v) {
    asm volatile("st.global.release.gpu.b32 [%0], %1;" :: "l"(p), "r"(v));
}

#define LDSM4(r, addr) asm volatile( \
    "ldmatrix.sync.aligned.m8n8.x4.shared.b16 {%0,%1,%2,%3}, [%4];" \
    : "=r"((r)[0]), "=r"((r)[1]), "=r"((r)[2]), "=r"((r)[3]) : "r"(addr))

#define MMA(d, a, b) asm volatile( \
    "mma.sync.aligned.m16n8k16.row.col.f32.f16.f16.f32 " \
    "{%0,%1,%2,%3}, {%4,%5,%6,%7}, {%8,%9}, {%0,%1,%2,%3};" \
    : "+f"((d)[0]), "+f"((d)[1]), "+f"((d)[2]), "+f"((d)[3]) \
    : "r"((a)[0]), "r"((a)[1]), "r"((a)[2]), "r"((a)[3]), "r"((b)[0]), "r"((b)[1]))

// ---------------- packing ---------------------------------------------------
static __device__ __forceinline__ float wval(int l, int row, int k,
                                             const float* W_ih0, const float* W_ihr,
                                             const float* W_hh, const float* b_ih,
                                             const float* b_hh) {
    if (k <= 48)      return W_hh[(l * G4 + row) * Hs + k];
    if (k == 49)      return b_ih[l * G4 + row] + b_hh[l * G4 + row];
    if (k <= 98) {
        int q = k - 50;
        return (l == 0) ? (q < IN0 ? W_ih0[row * IN0 + q] : 0.f)
                        : W_ihr[((l - 1) * G4 + row) * Hs + q];
    }
    return 0.f;
}

__global__ void pack_kernel(const float* __restrict__ W_ih0,
                            const float* __restrict__ W_ihr,
                            const float* __restrict__ W_hh,
                            const float* __restrict__ b_ih,
                            const float* __restrict__ b_hh) {
    int idx = blockIdx.x * blockDim.x + threadIdx.x;
    const int total = NL * NBP * KB;
    if (idx >= total) return;
    int l = idx / (NBP * KB);
    int rem = idx % (NBP * KB);
    int n = rem / KB, k = rem % KB;
    int u = n >> 2, j = n & 3;

    float w = (u < Hs) ? wval(l, j * Hs + u, k, W_ih0, W_ihr, W_hh, b_ih, b_hh) : 0.f;
    g_wpack[l][n][k] = __float2half_rn(w);
    if (u == 48)  // unit-48 scalar path W (fp32)
        g_w48[l][k][j] = w;
}

__global__ void reset_kernel() {
    int i = blockIdx.x * blockDim.x + threadIdx.x;
    if (i < NL * GB * 32) ((int*)g_flag)[i] = 0;
}

// ---------------- hybrid warp-MMA + scalar pipelined LSTM -------------------
__global__ __launch_bounds__(TPB, 1)
void lstm_mma(const float* __restrict__ xin) {
    extern __shared__ char sm[];
    const u32 Abase = smem_u32(sm);
    float* sw48 = (float*)(sm + 2 * ABUF);     // [KB][4]

    const int bid = blockIdx.x, l = bid / GB, g = bid % GB, bbase = g * BB;
    const int tid = threadIdx.x, ws = tid >> 5, lane = tid & 31;
    const bool mmaw = (ws < 8);
    const int tb = ws * 3;                      // 3 n-tiles per MMA warp, tiles 0..23

    // zero A buffers, stage W48
    for (int i = tid; i < 2 * ABUF / 4; i += TPB) ((u32*)sm)[i] = 0;
    for (int i = tid; i < KB * 4; i += TPB) sw48[i] = g_w48[l][0][i];

    // ---- persistent B fragments (MMA warps) ----
    u32 Bh[3][7][2];
    if (mmaw) {
#pragma unroll
        for (int nt = 0; nt < 3; nt++) {
            int n = (tb + nt) * 8 + (lane >> 2);
            const __half* wr = &g_wpack[l][n][0];
            int kb0 = (lane & 3) * 2;
#pragma unroll
            for (int kt = 0; kt < 7; kt++) {
                Bh[nt][kt][0] = *(const u32*)(wr + kt * 16 + kb0);
                Bh[nt][kt][1] = *(const u32*)(wr + kt * 16 + kb0 + 8);
            }
        }
    }
    __syncthreads();
    if (tid < BB) {   // bias-one column (49) in both buffers
        *(u16*)(sm + tid * AROW + 49 * 2)        = (u16)0x3C00;
        *(u16*)(sm + ABUF + tid * AROW + 49 * 2) = (u16)0x3C00;
    }

    const int* inflag  = &g_flag[(l == 0 ? 0 : l - 1)][g][0];
    int*       outflag = &g_flag[l][g][0];
    const u16* hxin    = &g_hx[(l == 0 ? 0 : l - 1)][0][0][0];
    u16*       hxout   = &g_hx[l][0][0][0];

    // staging identity (warps 8..10, 96 lanes)
    const int q = (ws - 8) * 32 + lane;          // 0..95
    const bool scal = (!mmaw) && (q < BB);       // unit-48 scalar lanes: row = q

    // ---- stage x(0) into buffer 0 (warps 8..10) ----
    if (!mmaw) {
        if (l > 0) {
            while (ldacq(inflag) < 1) __nanosleep(128);
            const u32* src = (const u32*)&hxin[(0 * BATCH + bbase) * HXU];
#pragma unroll
            for (int s = 0; s < 19; s++) {
                int w = q + 96 * s;
                if (w < BB * 28) {
                    int row = w / 28, cw = w % 28;
                    *(u32*)(sm + row * AROW + (50 + 2 * cw) * 2) = src[w];
                }
            }
        } else {
#pragma unroll
            for (int s = 0; s < 5; s++) {
                int w = q + 96 * s;
                if (w < BB * IN0) {
                    int row = w / IN0, c = w % IN0;
                    __half hb = __float2half_rn(xin[(bbase + row) * TT * IN0 + c]);
                    *(u16*)(sm + row * AROW + (50 + c) * 2) = __half_as_ushort(hb);
                }
            }
        }
    }
    __syncthreads();

    float cst[3][4];
#pragma unroll
    for (int nt = 0; nt < 3; nt++)
#pragma unroll
        for (int m = 0; m < 4; m++) cst[nt][m] = 0.f;
    float c48 = 0.f;

    const bool evenl = !(lane & 1);
    const bool loU   = !((lane >> 1) & 1);       // owns even unit of its pair
    const int arow15 = lane & 15;
    const int acolo  = (lane & 16) ? 8 : 0;

    for (int t = 0; t < TT; t++) {
        const int cur = t & 1, nxt = cur ^ 1;
        const u32 Acur = Abase + cur * ABUF;
        char* Acp = sm + cur * ABUF;
        char* Anx = sm + nxt * ABUF;
        const bool pf = (t + 1 < TT);

        if (mmaw) {
            // ---- MMA path: units 0..47, 24 n-tiles ----
            float acc[3][4][4];
#pragma unroll
            for (int nt = 0; nt < 3; nt++)
#pragma unroll
                for (int m = 0; m < 4; m++)
#pragma unroll
                    for (int e = 0; e < 4; e++) acc[nt][m][e] = 0.f;

#pragma unroll
            for (int kt = 0; kt < 7; kt++) {
                u32 a[4][4];
                const u32 cb = (u32)(kt * 16 + acolo) * 2;
#pragma unroll
                for (int m = 0; m < 4; m++) {
                    u32 ad = Acur + (u32)(m * 16 + arow15) * AROW + cb;
                    LDSM4(a[m], ad);
                }
#pragma unroll
                for (int m = 0; m < 4; m++)
#pragma unroll
                    for (int nt = 0; nt < 3; nt++)
                        MMA(acc[nt][m], a[m], Bh[nt][kt]);
            }

            // epilogue: shfl gate-gather, cell update, paired u32 stores
#pragma unroll
            for (int nt = 0; nt < 3; nt++) {
#pragma unroll
                for (int m = 0; m < 4; m++) {
                    float sA = evenl ? acc[nt][m][2] : acc[nt][m][0];
                    float sB = evenl ? acc[nt][m][3] : acc[nt][m][1];
                    float rA = __shfl_xor_sync(0xFFFFFFFFu, sA, 1);
                    float rB = __shfl_xor_sync(0xFFFFFFFFu, sB, 1);
                    float i_, f_, g_, o_; int row;
                    if (evenl) {
                        i_ = acc[nt][m][0]; f_ = acc[nt][m][1]; g_ = rA; o_ = rB;
                        row = m * 16 + (lane >> 2);
                    } else {
                        i_ = rA; f_ = rB; g_ = acc[nt][m][2]; o_ = acc[nt][m][3];
                        row = m * 16 + 8 + (lane >> 2);
                    }
                    float iv = sigf(i_), fv = sigf(f_), gv = tanha(g_), ov = sigf(o_);
                    float cc = fv * cst[nt][m] + iv * gv;
                    cst[nt][m] = cc;
                    float h = ov * tanha(cc);
                    // pair units u (even) and u^1 via shfl_xor(2): same row
                    u32 me = (u32)__half_as_ushort(__float2half_rn(h));
                    u32 pr = __shfl_xor_sync(0xFFFFFFFFu, me, 2);
                    if (loU) {
                        int unit = (tb + nt) * 2;          // even
                        u32 wde = me | (pr << 16);
                        *(u32*)(Anx + row * AROW + unit * 2) = wde;
                        *(u32*)&hxout[(t * BATCH + bbase + row) * HXU + unit] = wde;
                    }
                }
            }
        } else {
            // ---- scalar + staging path (warps 8..10) ----
            // prefetch x(t+1)
            u32 wv[19]; float xf[5];
            if (pf) {
                if (l > 0) {
                    while (ldacq(inflag) < t + 2) __nanosleep(128);
                    const u32* src = (const u32*)&hxin[((t + 1) * BATCH + bbase) * HXU];
#pragma unroll
                    for (int s = 0; s < 19; s++) {
                        int w = q + 96 * s;
                        if (w < BB * 28) wv[s] = src[w];
                    }
                } else {
#pragma unroll
                    for (int s = 0; s < 5; s++) {
                        int w = q + 96 * s;
                        if (w < BB * IN0)
                            xf[s] = xin[(bbase + w / IN0) * TT * IN0 + (t + 1) * IN0 + w % IN0];
                    }
                }
            }

            // unit-48 scalar gates (lanes 0..63 of warps 8,9): row = q
            if (scal) {
                const char* arow = Acp + q * AROW;
                float ai = 0.f, af = 0.f, ag = 0.f, ao = 0.f;
#pragma unroll 10
                for (int kp = 0; kp < 50; kp++) {       // cols 0..99
                    u32 w = *(const u32*)(arow + kp * 4);
                    __half_raw r0; r0.x = (u16)(w & 0xFFFF);
                    __half_raw r1; r1.x = (u16)(w >> 16);
                    float h0 = __half2float(__half(r0));
                    float h1 = __half2float(__half(r1));
                    float4 w0 = *(const float4*)(sw48 + (2 * kp) * 4);
                    float4 w1 = *(const float4*)(sw48 + (2 * kp + 1) * 4);
                    ai += h0 * w0.x + h1 * w1.x;
                    af += h0 * w0.y + h1 * w1.y;
                    ag += h0 * w0.z + h1 * w1.z;
                    ao += h0 * w0.w + h1 * w1.w;
                }
                float iv = sigf(ai), fv = sigf(af), gv = tanha(ag), ov = sigf(ao);
                c48 = fv * c48 + iv * gv;
                float h = ov * tanha(c48);
                u16 hb = __half_as_ushort(__float2half_rn(h));
                *(u16*)(Anx + q * AROW + 48 * 2) = hb;
                hxout[(t * BATCH + bbase + q) * HXU + 48] = hb;
            }

            // commit x(t+1)
            if (pf) {
                if (l > 0) {
#pragma unroll
                    for (int s = 0; s < 19; s++) {
                        int w = q + 96 * s;
                        if (w < BB * 28) {
                            int row = w / 28, cw = w % 28;
                            *(u32*)(Anx + row * AROW + (50 + 2 * cw) * 2) = wv[s];
                        }
                    }
                } else {
#pragma unroll
                    for (int s = 0; s < 5; s++) {
                        int w = q + 96 * s;
                        if (w < BB * IN0) {
                            __half hb = __float2half_rn(xf[s]);
                            *(u16*)(Anx + (w / IN0) * AROW + (50 + w % IN0) * 2) =
                                __half_as_ushort(hb);
                        }
                    }
                }
            }
        }

        __syncthreads();                         // single barrier per step
        if (tid == 0) strel(outflag, t + 1);     // publish h(t)
    }
}

// ---------------- final FC ---------------------------------------------------
#define FCB 128
__global__ void fc_kernel(const float* __restrict__ fc_w,
                          const float* __restrict__ fc_b,
                          float* __restrict__ outp) {
    __shared__ float sw[NOUT * Hs];
    __shared__ float sb[NOUT];
    const int t = blockIdx.x, bc = blockIdx.y, tid = threadIdx.x;

    for (int i = tid; i < NOUT * Hs; i += FCB) sw[i] = fc_w[i];
    if (tid < NOUT) sb[tid] = fc_b[tid];
    __syncthreads();

    const int b = bc * FCB + tid;
    const u32* hrow = (const u32*)&g_hx[NL - 1][t][b][0];
    float o[NOUT];
#pragma unroll
    for (int j = 0; j < NOUT; j++) o[j] = sb[j];
#pragma unroll
    for (int p = 0; p < 25; p++) {
        u32 w = hrow[p];
        __half_raw r0; r0.x = (u16)(w & 0xFFFF);
        __half_raw r1; r1.x = (u16)(w >> 16);
        float h0 = __half2float(__half(r0));
        float h1 = (2 * p + 1 < Hs) ? __half2float(__half(r1)) : 0.f;
#pragma unroll
        for (int j = 0; j < NOUT; j++) {
            o[j] += h0 * sw[j * Hs + 2 * p];
            if (2 * p + 1 < Hs) o[j] += h1 * sw[j * Hs + 2 * p + 1];
        }
    }
#pragma unroll
    for (int j = 0; j < NOUT; j++)
        outp[(b * TT + t) * NOUT + j] = o[j];
}

// ---------------- launcher ---------------------------------------------------
extern "C" void kernel_launch(void* const* d_in, const int* in_sizes, int n_in,
                              void* d_out, int out_size) {
    const float* x     = (const float*)d_in[0];
    const float* W_ih0 = (const float*)d_in[1];
    const float* W_ihr = (const float*)d_in[2];
    const float* W_hh  = (const float*)d_in[3];
    const float* b_ih  = (const float*)d_in[4];
    const float* b_hh  = (const float*)d_in[5];
    const float* fc_w  = (const float*)d_in[6];
    const float* fc_b  = (const float*)d_in[7];
    float* outp = (float*)d_out;

    cudaFuncSetAttribute(lstm_mma, cudaFuncAttributeMaxDynamicSharedMemorySize, SMEMB);

    const int total = NL * NBP * KB;
    pack_kernel<<<(total + 255) / 256, 256>>>(W_ih0, W_ihr, W_hh, b_ih, b_hh);
    reset_kernel<<<(NL * GB * 32 + 127) / 128, 128>>>();

    lstm_mma<<<NL * GB, TPB, SMEMB>>>(x);

    dim3 fcg(TT, BATCH / FCB);
    fc_kernel<<<fcg, FCB>>>(fc_w, fc_b, outp);
}

// round 17
// speedup vs baseline: 7.0127x; 1.0703x over previous
#include <cuda_runtime.h>
#include <cuda_fp16.h>

typedef unsigned int u32;
typedef unsigned short u16;

#define Hs     49
#define G4     196
#define NL     7
#define IN0    7
#define NOUT   7
#define BATCH  1024
#define TT     512

#define GB     16           // slices per layer -> 112 blocks
#define BB     64           // batch rows per block = MMA M
#define TPB    352          // 8 MMA warps + 3 scalar/staging warps
#define NBP    208          // packed B rows (52 units x 4 gates)
#define KB     112          // K: h 0..48 | bias 49 | x 50..98 | pad ..111
#define HXU    56           // u16 units per (t,b) row of g_hx

#define AROW   240          // A row stride bytes (15*16B -> LDSM conflict-free)
#define ABUF   (BB*AROW)    // 15360
#define SM_W48 (KB*4*4)     // 1792 B fp32 W for unit 48
#define SMEMB  (2*ABUF + SM_W48)

// ---------------- device scratch ------------------------------------------
__device__ __half g_wpack[NL][NBP][KB];
__device__ float  g_w48[NL][KB][4];        // unit-48 W, [k][gate] fp32
__device__ u16 g_hx[NL][TT][BATCH][HXU];   // h as fp16 (pads stay 0)
__device__ int g_flag[NL][GB][32];

// ---------------- helpers ---------------------------------------------------
static __device__ __forceinline__ u32 smem_u32(const void* p) {
    u32 a; asm("{ .reg .u64 t; cvta.to.shared.u64 t, %1; cvt.u32.u64 %0, t; }"
               : "=r"(a) : "l"(p)); return a;
}
static __device__ __forceinline__ float tanha(float x) {
    float r; asm("tanh.approx.f32 %0, %1;" : "=f"(r) : "f"(x)); return r;
}
static __device__ __forceinline__ float sigf(float x) {
    return fmaf(0.5f, tanha(0.5f * x), 0.5f);
}
static __device__ __forceinline__ u32 tanh2u(u32 x) {
    u32 r; asm("tanh.approx.f16x2 %0, %1;" : "=r"(r) : "r"(x)); return r;
}
static __device__ __forceinline__ int ldacq(const int* p) {
    int v; asm volatile("ld.global.acquire.gpu.b32 %0, [%1];" : "=r"(v) : "l"(p)); return v;
}
static __device__ __forceinline__ void strel(int* p, int v) {
    asm volatile("st.global.release.gpu.b32 [%0], %1;" :: "l"(p), "r"(v));
}

#define LDSM4(r, addr) asm volatile( \
    "ldmatrix.sync.aligned.m8n8.x4.shared.b16 {%0,%1,%2,%3}, [%4];" \
    : "=r"((r)[0]), "=r"((r)[1]), "=r"((r)[2]), "=r"((r)[3]) : "r"(addr))

#define MMA(d, a, b) asm volatile( \
    "mma.sync.aligned.m16n8k16.row.col.f32.f16.f16.f32 " \
    "{%0,%1,%2,%3}, {%4,%5,%6,%7}, {%8,%9}, {%0,%1,%2,%3};" \
    : "+f"((d)[0]), "+f"((d)[1]), "+f"((d)[2]), "+f"((d)[3]) \
    : "r"((a)[0]), "r"((a)[1]), "r"((a)[2]), "r"((a)[3]), "r"((b)[0]), "r"((b)[1]))

// ---------------- packing ---------------------------------------------------
static __device__ __forceinline__ float wval(int l, int row, int k,
                                             const float* W_ih0, const float* W_ihr,
                                             const float* W_hh, const float* b_ih,
                                             const float* b_hh) {
    if (k <= 48)      return W_hh[(l * G4 + row) * Hs + k];
    if (k == 49)      return b_ih[l * G4 + row] + b_hh[l * G4 + row];
    if (k <= 98) {
        int q = k - 50;
        return (l == 0) ? (q < IN0 ? W_ih0[row * IN0 + q] : 0.f)
                        : W_ihr[((l - 1) * G4 + row) * Hs + q];
    }
    return 0.f;
}

__global__ void pack_kernel(const float* __restrict__ W_ih0,
                            const float* __restrict__ W_ihr,
                            const float* __restrict__ W_hh,
                            const float* __restrict__ b_ih,
                            const float* __restrict__ b_hh) {
    int idx = blockIdx.x * blockDim.x + threadIdx.x;
    const int total = NL * NBP * KB;
    if (idx >= total) return;
    int l = idx / (NBP * KB);
    int rem = idx % (NBP * KB);
    int n = rem / KB, k = rem % KB;
    int u = n >> 2, j = n & 3;

    float w = (u < Hs) ? wval(l, j * Hs + u, k, W_ih0, W_ihr, W_hh, b_ih, b_hh) : 0.f;
    g_wpack[l][n][k] = __float2half_rn(w);
    if (u == 48)
        g_w48[l][k][j] = w;
}

__global__ void reset_kernel() {
    int i = blockIdx.x * blockDim.x + threadIdx.x;
    if (i < NL * GB * 32) ((int*)g_flag)[i] = 0;
}

// ---------------- hybrid warp-MMA + scalar pipelined LSTM -------------------
__global__ __launch_bounds__(TPB, 1)
void lstm_mma(const float* __restrict__ xin) {
    extern __shared__ char sm[];
    const u32 Abase = smem_u32(sm);
    float* sw48 = (float*)(sm + 2 * ABUF);     // [KB][4]

    const int bid = blockIdx.x, l = bid / GB, g = bid % GB, bbase = g * BB;
    const int tid = threadIdx.x, ws = tid >> 5, lane = tid & 31;
    const bool mmaw = (ws < 8);
    const int tb = ws * 3;                      // 3 n-tiles per MMA warp, tiles 0..23

    // zero A buffers, stage W48
    for (int i = tid; i < 2 * ABUF / 4; i += TPB) ((u32*)sm)[i] = 0;
    for (int i = tid; i < KB * 4; i += TPB) sw48[i] = g_w48[l][0][i];

    // ---- persistent B fragments (MMA warps) ----
    u32 Bh[3][7][2];
    if (mmaw) {
#pragma unroll
        for (int nt = 0; nt < 3; nt++) {
            int n = (tb + nt) * 8 + (lane >> 2);
            const __half* wr = &g_wpack[l][n][0];
            int kb0 = (lane & 3) * 2;
#pragma unroll
            for (int kt = 0; kt < 7; kt++) {
                Bh[nt][kt][0] = *(const u32*)(wr + kt * 16 + kb0);
                Bh[nt][kt][1] = *(const u32*)(wr + kt * 16 + kb0 + 8);
            }
        }
    }
    __syncthreads();
    if (tid < BB) {   // bias-one column (49) in both buffers
        *(u16*)(sm + tid * AROW + 49 * 2)        = (u16)0x3C00;
        *(u16*)(sm + ABUF + tid * AROW + 49 * 2) = (u16)0x3C00;
    }

    const int* inflag  = &g_flag[(l == 0 ? 0 : l - 1)][g][0];
    int*       outflag = &g_flag[l][g][0];
    const u16* hxin    = &g_hx[(l == 0 ? 0 : l - 1)][0][0][0];
    u16*       hxout   = &g_hx[l][0][0][0];

    // staging identity (warps 8..10, 96 lanes)
    const int q = (ws - 8) * 32 + lane;          // 0..95
    const bool scal = (!mmaw) && (q < BB);       // unit-48 scalar lanes: row = q

    // ---- stage x(0) into buffer 0 (warps 8..10) ----
    if (!mmaw) {
        if (l > 0) {
            while (ldacq(inflag) < 1) __nanosleep(128);
            const u32* src = (const u32*)&hxin[(0 * BATCH + bbase) * HXU];
#pragma unroll
            for (int s = 0; s < 19; s++) {
                int w = q + 96 * s;
                if (w < BB * 28) {
                    int row = w / 28, cw = w % 28;
                    *(u32*)(sm + row * AROW + (50 + 2 * cw) * 2) = src[w];
                }
            }
        } else {
#pragma unroll
            for (int s = 0; s < 5; s++) {
                int w = q + 96 * s;
                if (w < BB * IN0) {
                    int row = w / IN0, c = w % IN0;
                    __half hb = __float2half_rn(xin[(bbase + row) * TT * IN0 + c]);
                    *(u16*)(sm + row * AROW + (50 + c) * 2) = __half_as_ushort(hb);
                }
            }
        }
    }
    __syncthreads();

    float cst[3][4];
#pragma unroll
    for (int nt = 0; nt < 3; nt++)
#pragma unroll
        for (int m = 0; m < 4; m++) cst[nt][m] = 0.f;
    float c48 = 0.f;

    const bool evenl = !(lane & 1);
    const bool loU   = !((lane >> 1) & 1);       // owns even unit of its pair
    const int arow15 = lane & 15;
    const int acolo  = (lane & 16) ? 8 : 0;

    for (int t = 0; t < TT; t++) {
        const int cur = t & 1, nxt = cur ^ 1;
        const u32 Acur = Abase + cur * ABUF;
        char* Acp = sm + cur * ABUF;
        char* Anx = sm + nxt * ABUF;
        const bool pf = (t + 1 < TT);

        if (mmaw) {
            // ---- MMA path: units 0..47, 24 n-tiles ----
            float acc[3][4][4];
#pragma unroll
            for (int nt = 0; nt < 3; nt++)
#pragma unroll
                for (int m = 0; m < 4; m++)
#pragma unroll
                    for (int e = 0; e < 4; e++) acc[nt][m][e] = 0.f;

#pragma unroll
            for (int kt = 0; kt < 7; kt++) {
                u32 a[4][4];
                const u32 cb = (u32)(kt * 16 + acolo) * 2;
#pragma unroll
                for (int m = 0; m < 4; m++) {
                    u32 ad = Acur + (u32)(m * 16 + arow15) * AROW + cb;
                    LDSM4(a[m], ad);
                }
#pragma unroll
                for (int m = 0; m < 4; m++)
#pragma unroll
                    for (int nt = 0; nt < 3; nt++)
                        MMA(acc[nt][m], a[m], Bh[nt][kt]);
            }

            // epilogue: shfl gate-gather, f16x2 activations, paired u32 stores
            const __half2 H05 = __float2half2_rn(0.5f);
#pragma unroll
            for (int nt = 0; nt < 3; nt++) {
                const int unit = (tb + nt) * 2;          // even unit of pair
#pragma unroll
                for (int mp = 0; mp < 4; mp += 2) {
                    float iF[2], fF[2], gF[2], oF[2]; int row[2];
#pragma unroll
                    for (int e = 0; e < 2; e++) {
                        int m = mp + e;
                        float sA = evenl ? acc[nt][m][2] : acc[nt][m][0];
                        float sB = evenl ? acc[nt][m][3] : acc[nt][m][1];
                        float rA = __shfl_xor_sync(0xFFFFFFFFu, sA, 1);
                        float rB = __shfl_xor_sync(0xFFFFFFFFu, sB, 1);
                        if (evenl) {
                            iF[e] = acc[nt][m][0]; fF[e] = acc[nt][m][1];
                            gF[e] = rA;            oF[e] = rB;
                            row[e] = m * 16 + (lane >> 2);
                        } else {
                            iF[e] = rA;            fF[e] = rB;
                            gF[e] = acc[nt][m][2]; oF[e] = acc[nt][m][3];
                            row[e] = m * 16 + 8 + (lane >> 2);
                        }
                    }
                    // f16x2 activations (1 MUFU per 2 values)
                    __half2 i2 = __floats2half2_rn(iF[0], iF[1]);
                    __half2 f2 = __floats2half2_rn(fF[0], fF[1]);
                    __half2 g2 = __floats2half2_rn(gF[0], gF[1]);
                    __half2 o2 = __floats2half2_rn(oF[0], oF[1]);
                    i2 = __hmul2(i2, H05); *(u32*)&i2 = tanh2u(*(u32*)&i2);
                    i2 = __hfma2(i2, H05, H05);
                    f2 = __hmul2(f2, H05); *(u32*)&f2 = tanh2u(*(u32*)&f2);
                    f2 = __hfma2(f2, H05, H05);
                    o2 = __hmul2(o2, H05); *(u32*)&o2 = tanh2u(*(u32*)&o2);
                    o2 = __hfma2(o2, H05, H05);
                    *(u32*)&g2 = tanh2u(*(u32*)&g2);
                    // c update in fp32
                    float c0 = fmaf(__low2float(f2),  cst[nt][mp],
                                    __low2float(i2)  * __low2float(g2));
                    float c1 = fmaf(__high2float(f2), cst[nt][mp + 1],
                                    __high2float(i2) * __high2float(g2));
                    cst[nt][mp]     = c0;
                    cst[nt][mp + 1] = c1;
                    __half2 ct2 = __floats2half2_rn(c0, c1);
                    *(u32*)&ct2 = tanh2u(*(u32*)&ct2);
                    __half2 h2v = __hmul2(o2, ct2);
                    u32 hbits = *(u32*)&h2v;       // lo16 = h(row[0]), hi16 = h(row[1])
#pragma unroll
                    for (int e = 0; e < 2; e++) {
                        u32 me = (e == 0) ? (hbits & 0xFFFFu) : (hbits >> 16);
                        u32 pr = __shfl_xor_sync(0xFFFFFFFFu, me, 2);
                        if (loU) {
                            u32 wde = me | (pr << 16);
                            *(u32*)(Anx + row[e] * AROW + unit * 2) = wde;
                            *(u32*)&hxout[(t * BATCH + bbase + row[e]) * HXU + unit] = wde;
                        }
                    }
                }
            }
        } else {
            // ---- scalar + staging path (warps 8..10) ----
            u32 wv[19]; float xf[5];
            if (pf) {
                if (l > 0) {
                    while (ldacq(inflag) < t + 2) __nanosleep(128);
                    const u32* src = (const u32*)&hxin[((t + 1) * BATCH + bbase) * HXU];
#pragma unroll
                    for (int s = 0; s < 19; s++) {
                        int w = q + 96 * s;
                        if (w < BB * 28) wv[s] = src[w];
                    }
                } else {
#pragma unroll
                    for (int s = 0; s < 5; s++) {
                        int w = q + 96 * s;
                        if (w < BB * IN0)
                            xf[s] = xin[(bbase + w / IN0) * TT * IN0 + (t + 1) * IN0 + w % IN0];
                    }
                }
            }

            if (scal) {
                const char* arow = Acp + q * AROW;
                float ai = 0.f, af = 0.f, ag = 0.f, ao = 0.f;
#pragma unroll 10
                for (int kp = 0; kp < 50; kp++) {
                    u32 w = *(const u32*)(arow + kp * 4);
                    __half_raw r0; r0.x = (u16)(w & 0xFFFF);
                    __half_raw r1; r1.x = (u16)(w >> 16);
                    float h0 = __half2float(__half(r0));
                    float h1 = __half2float(__half(r1));
                    float4 w0 = *(const float4*)(sw48 + (2 * kp) * 4);
                    float4 w1 = *(const float4*)(sw48 + (2 * kp + 1) * 4);
                    ai += h0 * w0.x + h1 * w1.x;
                    af += h0 * w0.y + h1 * w1.y;
                    ag += h0 * w0.z + h1 * w1.z;
                    ao += h0 * w0.w + h1 * w1.w;
                }
                float iv = sigf(ai), fv = sigf(af), gv = tanha(ag), ov = sigf(ao);
                c48 = fv * c48 + iv * gv;
                float h = ov * tanha(c48);
                u16 hb = __half_as_ushort(__float2half_rn(h));
                *(u16*)(Anx + q * AROW + 48 * 2) = hb;
                hxout[(t * BATCH + bbase + q) * HXU + 48] = hb;
            }

            if (pf) {
                if (l > 0) {
#pragma unroll
                    for (int s = 0; s < 19; s++) {
                        int w = q + 96 * s;
                        if (w < BB * 28) {
                            int row = w / 28, cw = w % 28;
                            *(u32*)(Anx + row * AROW + (50 + 2 * cw) * 2) = wv[s];
                        }
                    }
                } else {
#pragma unroll
                    for (int s = 0; s < 5; s++) {
                        int w = q + 96 * s;
                        if (w < BB * IN0) {
                            __half hb = __float2half_rn(xf[s]);
                            *(u16*)(Anx + (w / IN0) * AROW + (50 + w % IN0) * 2) =
                                __half_as_ushort(hb);
                        }
                    }
                }
            }
        }

        __syncthreads();                         // single barrier per step
        if (tid == 0) strel(outflag, t + 1);     // publish h(t)
    }
}

// ---------------- final FC ---------------------------------------------------
#define FCB 128
__global__ void fc_kernel(const float* __restrict__ fc_w,
                          const float* __restrict__ fc_b,
                          float* __restrict__ outp) {
    __shared__ float sw[NOUT * Hs];
    __shared__ float sb[NOUT];
    const int t = blockIdx.x, bc = blockIdx.y, tid = threadIdx.x;

    for (int i = tid; i < NOUT * Hs; i += FCB) sw[i] = fc_w[i];
    if (tid < NOUT) sb[tid] = fc_b[tid];
    __syncthreads();

    const int b = bc * FCB + tid;
    const u32* hrow = (const u32*)&g_hx[NL - 1][t][b][0];
    float o[NOUT];
#pragma unroll
    for (int j = 0; j < NOUT; j++) o[j] = sb[j];
#pragma unroll
    for (int p = 0; p < 25; p++) {
        u32 w = hrow[p];
        __half_raw r0; r0.x = (u16)(w & 0xFFFF);
        __half_raw r1; r1.x = (u16)(w >> 16);
        float h0 = __half2float(__half(r0));
        float h1 = (2 * p + 1 < Hs) ? __half2float(__half(r1)) : 0.f;
#pragma unroll
        for (int j = 0; j < NOUT; j++) {
            o[j] += h0 * sw[j * Hs + 2 * p];
            if (2 * p + 1 < Hs) o[j] += h1 * sw[j * Hs + 2 * p + 1];
        }
    }
#pragma unroll
    for (int j = 0; j < NOUT; j++)
        outp[(b * TT + t) * NOUT + j] = o[j];
}

// ---------------- launcher ---------------------------------------------------
extern "C" void kernel_launch(void* const* d_in, const int* in_sizes, int n_in,
                              void* d_out, int out_size) {
    const float* x     = (const float*)d_in[0];
    const float* W_ih0 = (const float*)d_in[1];
    const float* W_ihr = (const float*)d_in[2];
    const float* W_hh  = (const float*)d_in[3];
    const float* b_ih  = (const float*)d_in[4];
    const float* b_hh  = (const float*)d_in[5];
    const float* fc_w  = (const float*)d_in[6];
    const float* fc_b  = (const float*)d_in[7];
    float* outp = (float*)d_out;

    cudaFuncSetAttribute(lstm_mma, cudaFuncAttributeMaxDynamicSharedMemorySize, SMEMB);

    const int total = NL * NBP * KB;
    pack_kernel<<<(total + 255) / 256, 256>>>(W_ih0, W_ihr, W_hh, b_ih, b_hh);
    reset_kernel<<<(NL * GB * 32 + 127) / 128, 128>>>();

    lstm_mma<<<NL * GB, TPB, SMEMB>>>(x);

    dim3 fcg(TT, BATCH / FCB);
    fc_kernel<<<fcg, FCB>>>(fc_w, fc_b, outp);
}